// round 1
// baseline (speedup 1.0000x reference)
#include <cuda_runtime.h>
#include <cuda_bf16.h>
#include <cstdint>

#define NV 100000
#define NE 300000
#define DH 128
#define LHID 12

// ---------------- scratch (static device globals; no allocation allowed) ---
__device__ float g_bufA[NV * DH];   // layer-1 output (pre-relu) = residual source
__device__ float g_bufB[NV * DH];
__device__ float g_bufC[NV * DH];
__device__ float g_bufN[NV * DH];   // neighbor-transform buffer
__device__ float g_bufNL[NV * 3];   // final-layer neighbor transform

// ---------------------------------------------------------------------------
// Fused dual GEMM: Y = X @ W0^T + b0  (cols 0..127 -> Yout)
//                  Nb = X @ W1^T + b1 (cols 128..255 -> Nbuf)
// X: [NV,128] row-major. Optional relu applied to X on load.
// Block: 256 thr, tile BM=64 rows x BN=256 cols, BK=16.
// Thread (ty=tid/32, tx=tid%32) owns rows ty*8+i, cols tx+32*j (conflict-free LDS).
// ---------------------------------------------------------------------------
__global__ __launch_bounds__(256, 2)
void gemm_dual(const float* __restrict__ X,
               const float* __restrict__ W0, const float* __restrict__ b0,
               const float* __restrict__ W1, const float* __restrict__ b1,
               float* __restrict__ Yout, float* __restrict__ Nbuf,
               int relu_in)
{
    __shared__ float xs[16][64];
    __shared__ float ws[16][256];

    const int tid = threadIdx.x;
    const int ty  = tid >> 5;       // 0..7
    const int tx  = tid & 31;       // 0..31
    const int m0  = blockIdx.x * 64;

    // this thread streams one weight row (col n = tid) into smem
    const float* Wrow = (tid < 128) ? (W0 + tid * 128) : (W1 + (tid - 128) * 128);

    float acc[8][8];
#pragma unroll
    for (int i = 0; i < 8; i++)
#pragma unroll
        for (int j = 0; j < 8; j++) acc[i][j] = 0.f;

    for (int kb = 0; kb < 128; kb += 16) {
        // ---- load X tile (64x16), transposed into xs[k][m] ----
        {
            int linear = tid * 4;        // 0..1023
            int m = linear >> 4;
            int k = linear & 15;
            int row = m0 + m;
            float4 v = make_float4(0.f, 0.f, 0.f, 0.f);
            if (row < NV) v = *(const float4*)(X + (size_t)row * 128 + kb + k);
            if (relu_in) {
                v.x = fmaxf(v.x, 0.f); v.y = fmaxf(v.y, 0.f);
                v.z = fmaxf(v.z, 0.f); v.w = fmaxf(v.w, 0.f);
            }
            xs[k + 0][m] = v.x; xs[k + 1][m] = v.y;
            xs[k + 2][m] = v.z; xs[k + 3][m] = v.w;
        }
        // ---- load W tile (256x16) into ws[k][n], n = tid ----
        {
            float4 w0 = *(const float4*)(Wrow + kb + 0);
            float4 w1 = *(const float4*)(Wrow + kb + 4);
            float4 w2 = *(const float4*)(Wrow + kb + 8);
            float4 w3 = *(const float4*)(Wrow + kb + 12);
            ws[0][tid]  = w0.x; ws[1][tid]  = w0.y; ws[2][tid]  = w0.z; ws[3][tid]  = w0.w;
            ws[4][tid]  = w1.x; ws[5][tid]  = w1.y; ws[6][tid]  = w1.z; ws[7][tid]  = w1.w;
            ws[8][tid]  = w2.x; ws[9][tid]  = w2.y; ws[10][tid] = w2.z; ws[11][tid] = w2.w;
            ws[12][tid] = w3.x; ws[13][tid] = w3.y; ws[14][tid] = w3.z; ws[15][tid] = w3.w;
        }
        __syncthreads();

#pragma unroll
        for (int k = 0; k < 16; k++) {
            float a[8], b[8];
#pragma unroll
            for (int i = 0; i < 8; i++) a[i] = xs[k][ty * 8 + i];   // warp-broadcast
#pragma unroll
            for (int j = 0; j < 8; j++) b[j] = ws[k][tx + 32 * j];  // conflict-free
#pragma unroll
            for (int i = 0; i < 8; i++)
#pragma unroll
                for (int j = 0; j < 8; j++) acc[i][j] += a[i] * b[j];
        }
        __syncthreads();
    }

    // ---- epilogue: bias + split into Y / Nbuf (coalesced scalar stores) ----
#pragma unroll
    for (int j = 0; j < 8; j++) {
        int n = tx + 32 * j;
        float bias = (n < 128) ? b0[n] : b1[n - 128];
        float* dst = (n < 128) ? (Yout + n) : (Nbuf + (n - 128));
#pragma unroll
        for (int i = 0; i < 8; i++) {
            int row = m0 + ty * 8 + i;
            if (row < NV) dst[(size_t)row * 128] = acc[i][j] + bias;
        }
    }
}

// ---------------------------------------------------------------------------
// Undirected edge scatter: out[i] += n[j]; out[j] += n[i]  (128 floats each)
// One warp per edge; each lane handles one float4; vector red.add.v4.f32.
// ---------------------------------------------------------------------------
__global__ __launch_bounds__(256)
void scatter_add(const float4* __restrict__ Nb, const int2* __restrict__ edges,
                 float* __restrict__ Out)
{
    int w = (blockIdx.x * blockDim.x + threadIdx.x) >> 5;
    int lane = threadIdx.x & 31;
    if (w >= NE) return;
    int2 e = edges[w];
    float4 vj = Nb[(size_t)e.y * 32 + lane];
    float4 vi = Nb[(size_t)e.x * 32 + lane];
    float* pi = Out + (size_t)e.x * 128 + lane * 4;
    float* pj = Out + (size_t)e.y * 128 + lane * 4;
    asm volatile("red.global.add.v4.f32 [%0], {%1,%2,%3,%4};"
                 :: "l"(pi), "f"(vj.x), "f"(vj.y), "f"(vj.z), "f"(vj.w) : "memory");
    asm volatile("red.global.add.v4.f32 [%0], {%1,%2,%3,%4};"
                 :: "l"(pj), "f"(vi.x), "f"(vi.y), "f"(vi.z), "f"(vi.w) : "memory");
}

// ---------------------------------------------------------------------------
// Final layer: z = relu(Xa) + relu(Xb); y = z@W0l^T + b0l; n = z@W1l^T + b1l
// One warp per row; 6 dot products of length 128 via lane-partials + shfl.
// ---------------------------------------------------------------------------
__global__ __launch_bounds__(256)
void final_gemm(const float* __restrict__ Xa, const float* __restrict__ Xb,
                const float* __restrict__ W0, const float* __restrict__ b0,
                const float* __restrict__ W1, const float* __restrict__ b1,
                float* __restrict__ Yout /*NV*3*/, float* __restrict__ Nl /*NV*3*/)
{
    __shared__ float w[6][128];
    int tid = threadIdx.x;
    for (int i = tid; i < 384; i += blockDim.x) {
        w[i / 128][i % 128]     = W0[i];
        w[3 + i / 128][i % 128] = W1[i];
    }
    __syncthreads();

    int row  = blockIdx.x * (blockDim.x >> 5) + (tid >> 5);
    int lane = tid & 31;
    if (row >= NV) return;

    float4 a = ((const float4*)(Xa + (size_t)row * 128))[lane];
    float4 b = ((const float4*)(Xb + (size_t)row * 128))[lane];
    float4 z;
    z.x = fmaxf(a.x, 0.f) + fmaxf(b.x, 0.f);
    z.y = fmaxf(a.y, 0.f) + fmaxf(b.y, 0.f);
    z.z = fmaxf(a.z, 0.f) + fmaxf(b.z, 0.f);
    z.w = fmaxf(a.w, 0.f) + fmaxf(b.w, 0.f);

    float s[6];
#pragma unroll
    for (int o = 0; o < 6; o++) {
        float4 wv = ((const float4*)w[o])[lane];
        s[o] = z.x * wv.x + z.y * wv.y + z.z * wv.z + z.w * wv.w;
    }
#pragma unroll
    for (int off = 16; off > 0; off >>= 1)
#pragma unroll
        for (int o = 0; o < 6; o++)
            s[o] += __shfl_down_sync(0xffffffffu, s[o], off);

    if (lane == 0) {
#pragma unroll
        for (int o = 0; o < 3; o++) {
            Yout[(size_t)row * 3 + o] = s[o] + b0[o];
            Nl[(size_t)row * 3 + o]   = s[3 + o] + b1[o];
        }
    }
}

// Final scatter over D_OUT=3: one thread per edge, scalar atomics.
__global__ __launch_bounds__(256)
void scatter3(const float* __restrict__ Nl, const int2* __restrict__ edges,
              float* __restrict__ Out)
{
    int t = blockIdx.x * blockDim.x + threadIdx.x;
    if (t >= NE) return;
    int2 e = edges[t];
#pragma unroll
    for (int o = 0; o < 3; o++) {
        atomicAdd(Out + (size_t)e.x * 3 + o, Nl[(size_t)e.y * 3 + o]);
        atomicAdd(Out + (size_t)e.y * 3 + o, Nl[(size_t)e.x * 3 + o]);
    }
}

// auxiliary = relu(last hidden output)
__global__ __launch_bounds__(256)
void relu_copy(const float4* __restrict__ in, float4* __restrict__ out, int n4)
{
    int i = blockIdx.x * blockDim.x + threadIdx.x;
    if (i >= n4) return;
    float4 v = in[i];
    v.x = fmaxf(v.x, 0.f); v.y = fmaxf(v.y, 0.f);
    v.z = fmaxf(v.z, 0.f); v.w = fmaxf(v.w, 0.f);
    out[i] = v;
}

// ---------------------------------------------------------------------------
extern "C" void kernel_launch(void* const* d_in, const int* in_sizes, int n_in,
                              void* d_out, int out_size)
{
    const float* features = (const float*)d_in[0];
    const int2*  edges    = (const int2*)d_in[1];
    const float* W0_1 = (const float*)d_in[2];
    const float* b0_1 = (const float*)d_in[3];
    const float* W1_1 = (const float*)d_in[4];
    const float* b1_1 = (const float*)d_in[5];
    const float* W0_h = (const float*)d_in[6];
    const float* b0_h = (const float*)d_in[7];
    const float* W1_h = (const float*)d_in[8];
    const float* b1_h = (const float*)d_in[9];
    const float* W0_l = (const float*)d_in[10];
    const float* b0_l = (const float*)d_in[11];
    const float* W1_l = (const float*)d_in[12];
    const float* b1_l = (const float*)d_in[13];
    float* out = (float*)d_out;   // [vertices NV*3 | auxiliary NV*128]

    float *bufA, *bufB, *bufC, *bufN, *bufNL;
    cudaGetSymbolAddress((void**)&bufA,  g_bufA);
    cudaGetSymbolAddress((void**)&bufB,  g_bufB);
    cudaGetSymbolAddress((void**)&bufC,  g_bufC);
    cudaGetSymbolAddress((void**)&bufN,  g_bufN);
    cudaGetSymbolAddress((void**)&bufNL, g_bufNL);

    const int gemmBlocks    = (NV + 63) / 64;           // 1563
    const int scatterBlocks = (NE * 32 + 255) / 256;    // warp per edge

    // ---- layer 1 (in -> hidden), no relu on input ----
    gemm_dual<<<gemmBlocks, 256>>>(features, W0_1, b0_1, W1_1, b1_1, bufA, bufN, 0);
    scatter_add<<<scatterBlocks, 256>>>((const float4*)bufN, edges, bufA);

    // ---- 12 hidden layers (relu on input), ping-pong B/C, preserve A ----
    const float* in = bufA;
    float* o1 = bufB;
    float* o2 = bufC;
    for (int l = 0; l < LHID; l++) {
        gemm_dual<<<gemmBlocks, 256>>>(in, W0_h + l * DH * DH, b0_h + l * DH,
                                       W1_h + l * DH * DH, b1_h + l * DH,
                                       o1, bufN, 1);
        scatter_add<<<scatterBlocks, 256>>>((const float4*)bufN, edges, o1);
        in = o1;
        float* t = o1; o1 = o2; o2 = t;
    }
    // `in` now holds pre-relu output of last hidden layer.

    // ---- final layer: z = relu(bufA) + relu(in) ----
    final_gemm<<<(NV + 7) / 8, 256>>>(bufA, in, W0_l, b0_l, W1_l, b1_l, out, bufNL);
    scatter3<<<(NE + 255) / 256, 256>>>(bufNL, edges, out);

    // ---- auxiliary = relu(in) ----
    relu_copy<<<(NV * 32 + 255) / 256, 256>>>((const float4*)in,
                                              (float4*)(out + (size_t)NV * 3), NV * 32);
}

// round 3
// speedup vs baseline: 1.6705x; 1.6705x over previous
#include <cuda_runtime.h>
#include <cuda_bf16.h>
#include <cstdint>

#define NV 100000
#define NE 300000
#define DH 128
#define LHID 12

// ---------------- scratch (static device globals; no allocation allowed) ---
__device__ float g_bufA[NV * DH];   // layer-1 output (pre-relu) = residual source
__device__ float g_bufB[NV * DH];
__device__ float g_bufC[NV * DH];
__device__ float g_bufN[NV * DH];   // neighbor-transform buffer
__device__ float g_bufNL[NV * 3];   // final-layer neighbor transform

// ======================= helpers ===========================================
__device__ __forceinline__ uint32_t smem_u32(const void* p) {
    uint32_t a;
    asm("{ .reg .u64 t; cvta.to.shared.u64 t, %1; cvt.u32.u64 %0, t; }"
        : "=r"(a) : "l"(p));
    return a;
}
__device__ __forceinline__ void ldmatrix_x4(uint32_t* r, uint32_t addr) {
    asm volatile("ldmatrix.sync.aligned.m8n8.x4.shared.b16 {%0,%1,%2,%3}, [%4];"
                 : "=r"(r[0]), "=r"(r[1]), "=r"(r[2]), "=r"(r[3]) : "r"(addr));
}
__device__ __forceinline__ void mma16816(float* c, const uint32_t* a, const uint32_t* b) {
    asm volatile(
        "mma.sync.aligned.m16n8k16.row.col.f32.bf16.bf16.f32 "
        "{%0,%1,%2,%3}, {%4,%5,%6,%7}, {%8,%9}, {%0,%1,%2,%3};"
        : "+f"(c[0]), "+f"(c[1]), "+f"(c[2]), "+f"(c[3])
        : "r"(a[0]), "r"(a[1]), "r"(a[2]), "r"(a[3]), "r"(b[0]), "r"(b[1]));
}
__device__ __forceinline__ uint32_t pk(__nv_bfloat16 a, __nv_bfloat16 b) {
    uint16_t ua = *(uint16_t*)&a, ub = *(uint16_t*)&b;
    return (uint32_t)ua | ((uint32_t)ub << 16);
}

// SMEM layout (bytes). Row stride 272 = 17*16B -> conflict-free ldmatrix.
#define TSTR 272
#define OFF_BIAS 0
#define OFF_AH   1024
#define OFF_AL   (OFF_AH + 64 * TSTR)      // 18432
#define OFF_BH   (OFF_AL + 64 * TSTR)      // 35840
#define OFF_BL   (OFF_BH + 256 * TSTR)     // 105472
#define SMEM_TOTAL (OFF_BL + 256 * TSTR)   // 175104

// ---------------------------------------------------------------------------
// Tensor-core dual GEMM via mma.sync bf16 with hi/lo split (fp32-class):
//   Yout[m,0:128] = X @ W0^T + b0 ;  Nbuf[m,0:128] = X @ W1^T + b1
// CTA: 64 rows x 256 cols, K=128 resident. 8 warps = 2(M) x 4(N), warp 32x64.
// ---------------------------------------------------------------------------
__global__ __launch_bounds__(256, 1)
void gemm_dual_tc(const float* __restrict__ X,
                  const float* __restrict__ W0, const float* __restrict__ b0,
                  const float* __restrict__ W1, const float* __restrict__ b1,
                  float* __restrict__ Yout, float* __restrict__ Nbuf,
                  int relu_in)
{
    extern __shared__ char smem[];
    const uint32_t sb = smem_u32(smem);
    const int tid  = threadIdx.x;
    const int wid  = tid >> 5;
    const int lane = tid & 31;
    const int m0   = blockIdx.x * 64;

    // bias into smem (256 threads, 256 values)
    ((float*)(smem + OFF_BIAS))[tid] = (tid < 128) ? b0[tid] : b1[tid - 128];

    // ---- A tile: 64 rows x 128 k, fp32 -> (hi,lo) bf16 ----
#pragma unroll
    for (int i = 0; i < 8; i++) {
        int idx = tid + i * 256;
        int r  = idx >> 5;
        int c4 = (idx & 31) * 4;
        int grow = m0 + r;
        float4 v = make_float4(0.f, 0.f, 0.f, 0.f);
        if (grow < NV) v = *(const float4*)(X + (size_t)grow * 128 + c4);
        if (relu_in) {
            v.x = fmaxf(v.x, 0.f); v.y = fmaxf(v.y, 0.f);
            v.z = fmaxf(v.z, 0.f); v.w = fmaxf(v.w, 0.f);
        }
        __nv_bfloat16 h0 = __float2bfloat16_rn(v.x), h1 = __float2bfloat16_rn(v.y);
        __nv_bfloat16 h2 = __float2bfloat16_rn(v.z), h3 = __float2bfloat16_rn(v.w);
        float l0 = v.x - __bfloat162float(h0), l1 = v.y - __bfloat162float(h1);
        float l2 = v.z - __bfloat162float(h2), l3 = v.w - __bfloat162float(h3);
        uint32_t off = (uint32_t)(r * TSTR + c4 * 2);
        *(uint2*)(smem + OFF_AH + off) = make_uint2(pk(h0, h1), pk(h2, h3));
        *(uint2*)(smem + OFF_AL + off) =
            make_uint2(pk(__float2bfloat16_rn(l0), __float2bfloat16_rn(l1)),
                       pk(__float2bfloat16_rn(l2), __float2bfloat16_rn(l3)));
    }

    // ---- B tile: 256 rows (W0 then W1) x 128 k ----
#pragma unroll
    for (int i = 0; i < 32; i++) {
        int idx = tid + i * 256;
        int n  = idx >> 5;
        int c4 = (idx & 31) * 4;
        const float* Wrow = (n < 128) ? (W0 + (size_t)n * 128)
                                      : (W1 + (size_t)(n - 128) * 128);
        float4 v = *(const float4*)(Wrow + c4);
        __nv_bfloat16 h0 = __float2bfloat16_rn(v.x), h1 = __float2bfloat16_rn(v.y);
        __nv_bfloat16 h2 = __float2bfloat16_rn(v.z), h3 = __float2bfloat16_rn(v.w);
        float l0 = v.x - __bfloat162float(h0), l1 = v.y - __bfloat162float(h1);
        float l2 = v.z - __bfloat162float(h2), l3 = v.w - __bfloat162float(h3);
        uint32_t off = (uint32_t)(n * TSTR + c4 * 2);
        *(uint2*)(smem + OFF_BH + off) = make_uint2(pk(h0, h1), pk(h2, h3));
        *(uint2*)(smem + OFF_BL + off) =
            make_uint2(pk(__float2bfloat16_rn(l0), __float2bfloat16_rn(l1)),
                       pk(__float2bfloat16_rn(l2), __float2bfloat16_rn(l3)));
    }
    __syncthreads();

    // ---- warp tiling: wm in {0,1} (rows), wn in {0..3} (cols) ----
    const int wm = wid & 1;
    const int wn = wid >> 1;

    // ldmatrix lane addresses
    const uint32_t a_row   = (uint32_t)(wm * 32 + (lane & 15));
    const uint32_t a_kh    = (uint32_t)((lane >> 4) * 8);
    const uint32_t a_base  = sb + OFF_AH + a_row * TSTR + a_kh * 2;
    const uint32_t b_n     = (uint32_t)(wn * 64 + (lane & 7) + ((lane >> 4) * 8));
    const uint32_t b_kh    = (uint32_t)(((lane >> 3) & 1) * 8);
    const uint32_t b_base  = sb + OFF_BH + b_n * TSTR + b_kh * 2;

    float acc[2][8][4];
#pragma unroll
    for (int mt = 0; mt < 2; mt++)
#pragma unroll
        for (int nt = 0; nt < 8; nt++)
#pragma unroll
            for (int q = 0; q < 4; q++) acc[mt][nt][q] = 0.f;

#pragma unroll
    for (int s = 0; s < 8; s++) {
        uint32_t Ah[2][4], Al[2][4], Bh[4][4], Bl[4][4];
#pragma unroll
        for (int mt = 0; mt < 2; mt++) {
            uint32_t ad = a_base + (uint32_t)(mt * 16 * TSTR + s * 32);
            ldmatrix_x4(Ah[mt], ad);
            ldmatrix_x4(Al[mt], ad + (OFF_AL - OFF_AH));
        }
#pragma unroll
        for (int p = 0; p < 4; p++) {
            uint32_t bd = b_base + (uint32_t)(p * 16 * TSTR + s * 32);
            ldmatrix_x4(Bh[p], bd);
            ldmatrix_x4(Bl[p], bd + (OFF_BL - OFF_BH));
        }
#pragma unroll
        for (int mt = 0; mt < 2; mt++)
#pragma unroll
            for (int nt = 0; nt < 8; nt++) {
                const uint32_t* bh = &Bh[nt >> 1][(nt & 1) * 2];
                const uint32_t* bl = &Bl[nt >> 1][(nt & 1) * 2];
                mma16816(acc[mt][nt], Ah[mt], bh);   // hi*hi
                mma16816(acc[mt][nt], Al[mt], bh);   // lo*hi
                mma16816(acc[mt][nt], Ah[mt], bl);   // hi*lo
            }
    }

    // ---- epilogue: bias + guarded float2 stores ----
    const int g = lane >> 2;
    const int t = lane & 3;
    const bool isY = (wn < 2);
    float* dbase = isY ? Yout : Nbuf;
    const float* bs = (const float*)(smem + OFF_BIAS);
#pragma unroll
    for (int mt = 0; mt < 2; mt++) {
        int row0 = m0 + wm * 32 + mt * 16 + g;
#pragma unroll
        for (int nt = 0; nt < 8; nt++) {
            int col = wn * 64 + nt * 8 + t * 2;
            float b0v = bs[col], b1v = bs[col + 1];
            int cc = isY ? col : (col - 128);
            if (row0 < NV) {
                float2 o = make_float2(acc[mt][nt][0] + b0v, acc[mt][nt][1] + b1v);
                *(float2*)(dbase + (size_t)row0 * 128 + cc) = o;
            }
            if (row0 + 8 < NV) {
                float2 o = make_float2(acc[mt][nt][2] + b0v, acc[mt][nt][3] + b1v);
                *(float2*)(dbase + (size_t)(row0 + 8) * 128 + cc) = o;
            }
        }
    }
}

// ---------------------------------------------------------------------------
// Undirected edge scatter: out[i] += n[j]; out[j] += n[i]  (128 floats each)
// One warp per edge; each lane handles one float4; vector red.add.v4.f32.
// ---------------------------------------------------------------------------
__global__ __launch_bounds__(256)
void scatter_add(const float4* __restrict__ Nb, const int2* __restrict__ edges,
                 float* __restrict__ Out)
{
    int w = (blockIdx.x * blockDim.x + threadIdx.x) >> 5;
    int lane = threadIdx.x & 31;
    if (w >= NE) return;
    int2 e = edges[w];
    float4 vj = Nb[(size_t)e.y * 32 + lane];
    float4 vi = Nb[(size_t)e.x * 32 + lane];
    float* pi = Out + (size_t)e.x * 128 + lane * 4;
    float* pj = Out + (size_t)e.y * 128 + lane * 4;
    asm volatile("red.global.add.v4.f32 [%0], {%1,%2,%3,%4};"
                 :: "l"(pi), "f"(vj.x), "f"(vj.y), "f"(vj.z), "f"(vj.w) : "memory");
    asm volatile("red.global.add.v4.f32 [%0], {%1,%2,%3,%4};"
                 :: "l"(pj), "f"(vi.x), "f"(vi.y), "f"(vi.z), "f"(vi.w) : "memory");
}

// ---------------------------------------------------------------------------
// Final layer: z = relu(Xa) + relu(Xb); y = z@W0l^T + b0l; n = z@W1l^T + b1l
// ---------------------------------------------------------------------------
__global__ __launch_bounds__(256)
void final_gemm(const float* __restrict__ Xa, const float* __restrict__ Xb,
                const float* __restrict__ W0, const float* __restrict__ b0,
                const float* __restrict__ W1, const float* __restrict__ b1,
                float* __restrict__ Yout /*NV*3*/, float* __restrict__ Nl /*NV*3*/)
{
    __shared__ float w[6][128];
    int tid = threadIdx.x;
    for (int i = tid; i < 384; i += blockDim.x) {
        w[i / 128][i % 128]     = W0[i];
        w[3 + i / 128][i % 128] = W1[i];
    }
    __syncthreads();

    int row  = blockIdx.x * (blockDim.x >> 5) + (tid >> 5);
    int lane = tid & 31;
    if (row >= NV) return;

    float4 a = ((const float4*)(Xa + (size_t)row * 128))[lane];
    float4 b = ((const float4*)(Xb + (size_t)row * 128))[lane];
    float4 z;
    z.x = fmaxf(a.x, 0.f) + fmaxf(b.x, 0.f);
    z.y = fmaxf(a.y, 0.f) + fmaxf(b.y, 0.f);
    z.z = fmaxf(a.z, 0.f) + fmaxf(b.z, 0.f);
    z.w = fmaxf(a.w, 0.f) + fmaxf(b.w, 0.f);

    float s[6];
#pragma unroll
    for (int o = 0; o < 6; o++) {
        float4 wv = ((const float4*)w[o])[lane];
        s[o] = z.x * wv.x + z.y * wv.y + z.z * wv.z + z.w * wv.w;
    }
#pragma unroll
    for (int off = 16; off > 0; off >>= 1)
#pragma unroll
        for (int o = 0; o < 6; o++)
            s[o] += __shfl_down_sync(0xffffffffu, s[o], off);

    if (lane == 0) {
#pragma unroll
        for (int o = 0; o < 3; o++) {
            Yout[(size_t)row * 3 + o] = s[o] + b0[o];
            Nl[(size_t)row * 3 + o]   = s[3 + o] + b1[o];
        }
    }
}

// Final scatter over D_OUT=3: one thread per edge, scalar atomics.
__global__ __launch_bounds__(256)
void scatter3(const float* __restrict__ Nl, const int2* __restrict__ edges,
              float* __restrict__ Out)
{
    int t = blockIdx.x * blockDim.x + threadIdx.x;
    if (t >= NE) return;
    int2 e = edges[t];
#pragma unroll
    for (int o = 0; o < 3; o++) {
        atomicAdd(Out + (size_t)e.x * 3 + o, Nl[(size_t)e.y * 3 + o]);
        atomicAdd(Out + (size_t)e.y * 3 + o, Nl[(size_t)e.x * 3 + o]);
    }
}

// auxiliary = relu(last hidden output)
__global__ __launch_bounds__(256)
void relu_copy(const float4* __restrict__ in, float4* __restrict__ out, int n4)
{
    int i = blockIdx.x * blockDim.x + threadIdx.x;
    if (i >= n4) return;
    float4 v = in[i];
    v.x = fmaxf(v.x, 0.f); v.y = fmaxf(v.y, 0.f);
    v.z = fmaxf(v.z, 0.f); v.w = fmaxf(v.w, 0.f);
    out[i] = v;
}

// ---------------------------------------------------------------------------
extern "C" void kernel_launch(void* const* d_in, const int* in_sizes, int n_in,
                              void* d_out, int out_size)
{
    const float* features = (const float*)d_in[0];
    const int2*  edges    = (const int2*)d_in[1];
    const float* W0_1 = (const float*)d_in[2];
    const float* b0_1 = (const float*)d_in[3];
    const float* W1_1 = (const float*)d_in[4];
    const float* b1_1 = (const float*)d_in[5];
    const float* W0_h = (const float*)d_in[6];
    const float* b0_h = (const float*)d_in[7];
    const float* W1_h = (const float*)d_in[8];
    const float* b1_h = (const float*)d_in[9];
    const float* W0_l = (const float*)d_in[10];
    const float* b0_l = (const float*)d_in[11];
    const float* W1_l = (const float*)d_in[12];
    const float* b1_l = (const float*)d_in[13];
    float* out = (float*)d_out;   // [vertices NV*3 | auxiliary NV*128]

    float *bufA, *bufB, *bufC, *bufN, *bufNL;
    cudaGetSymbolAddress((void**)&bufA,  g_bufA);
    cudaGetSymbolAddress((void**)&bufB,  g_bufB);
    cudaGetSymbolAddress((void**)&bufC,  g_bufC);
    cudaGetSymbolAddress((void**)&bufN,  g_bufN);
    cudaGetSymbolAddress((void**)&bufNL, g_bufNL);

    cudaFuncSetAttribute(gemm_dual_tc,
                         cudaFuncAttributeMaxDynamicSharedMemorySize, SMEM_TOTAL);

    const int gemmBlocks    = (NV + 63) / 64;           // 1563
    const int scatterBlocks = (NE * 32 + 255) / 256;    // warp per edge

    // ---- layer 1 (in -> hidden), no relu on input ----
    gemm_dual_tc<<<gemmBlocks, 256, SMEM_TOTAL>>>(features, W0_1, b0_1, W1_1, b1_1,
                                                  bufA, bufN, 0);
    scatter_add<<<scatterBlocks, 256>>>((const float4*)bufN, edges, bufA);

    // ---- 12 hidden layers (relu on input), ping-pong B/C, preserve A ----
    const float* in = bufA;
    float* o1 = bufB;
    float* o2 = bufC;
    for (int l = 0; l < LHID; l++) {
        gemm_dual_tc<<<gemmBlocks, 256, SMEM_TOTAL>>>(in, W0_h + l * DH * DH, b0_h + l * DH,
                                                      W1_h + l * DH * DH, b1_h + l * DH,
                                                      o1, bufN, 1);
        scatter_add<<<scatterBlocks, 256>>>((const float4*)bufN, edges, o1);
        in = o1;
        float* t = o1; o1 = o2; o2 = t;
    }
    // `in` now holds pre-relu output of last hidden layer.

    // ---- final layer: z = relu(bufA) + relu(in) ----
    final_gemm<<<(NV + 7) / 8, 256>>>(bufA, in, W0_l, b0_l, W1_l, b1_l, out, bufNL);
    scatter3<<<(NE + 255) / 256, 256>>>(bufNL, edges, out);

    // ---- auxiliary = relu(in) ----
    relu_copy<<<(NV * 32 + 255) / 256, 256>>>((const float4*)in,
                                              (float4*)(out + (size_t)NV * 3), NV * 32);
}

// round 4
// speedup vs baseline: 2.0241x; 1.2117x over previous
#include <cuda_runtime.h>
#include <cuda_bf16.h>
#include <cstdint>

#define NV 100000
#define NE 300000
#define DH 128
#define LHID 12
#define NB_SCAN 98   // ceil(NV/1024)

// ---------------- scratch (static device globals; no allocation allowed) ---
__device__ float g_Y[NV * DH];              // self-transform output (fp32)
__device__ float g_N[NV * DH];              // neighbor-transform output (fp32)
__device__ __nv_bfloat16 g_Ah[NV * DH];     // current layer input, hi plane
__device__ __nv_bfloat16 g_Al[NV * DH];     // current layer input, lo plane
__device__ __nv_bfloat16 g_Rh[NV * DH];     // residual (layer-1 out) hi
__device__ __nv_bfloat16 g_Rl[NV * DH];     // residual lo
__device__ __nv_bfloat16 g_WH[13 * 256 * DH];  // pre-split weights hi (W0|W1 per layer)
__device__ __nv_bfloat16 g_WL[13 * 256 * DH];  // pre-split weights lo
__device__ float g_NL[NV * 3];              // final-layer neighbor transform
// CSR build
__device__ int g_deg[NV];
__device__ int g_incl[NV];
__device__ int g_bsum[NB_SCAN];
__device__ int g_indptr[NV + 1];
__device__ int g_cursor[NV];
__device__ int g_adj[2 * NE];

// ======================= helpers ===========================================
__device__ __forceinline__ uint32_t smem_u32(const void* p) {
    uint32_t a;
    asm("{ .reg .u64 t; cvta.to.shared.u64 t, %1; cvt.u32.u64 %0, t; }"
        : "=r"(a) : "l"(p));
    return a;
}
__device__ __forceinline__ void ldmatrix_x4(uint32_t* r, uint32_t addr) {
    asm volatile("ldmatrix.sync.aligned.m8n8.x4.shared.b16 {%0,%1,%2,%3}, [%4];"
                 : "=r"(r[0]), "=r"(r[1]), "=r"(r[2]), "=r"(r[3]) : "r"(addr));
}
__device__ __forceinline__ void mma16816(float* c, const uint32_t* a, const uint32_t* b) {
    asm volatile(
        "mma.sync.aligned.m16n8k16.row.col.f32.bf16.bf16.f32 "
        "{%0,%1,%2,%3}, {%4,%5,%6,%7}, {%8,%9}, {%0,%1,%2,%3};"
        : "+f"(c[0]), "+f"(c[1]), "+f"(c[2]), "+f"(c[3])
        : "r"(a[0]), "r"(a[1]), "r"(a[2]), "r"(a[3]), "r"(b[0]), "r"(b[1]));
}
__device__ __forceinline__ uint32_t pk(__nv_bfloat16 a, __nv_bfloat16 b) {
    uint16_t ua = *(uint16_t*)&a, ub = *(uint16_t*)&b;
    return (uint32_t)ua | ((uint32_t)ub << 16);
}
__device__ __forceinline__ float2 up2(uint32_t p) {
    __nv_bfloat162 b = *reinterpret_cast<__nv_bfloat162*>(&p);
    return make_float2(__bfloat162float(b.x), __bfloat162float(b.y));
}
__device__ __forceinline__ void cp16(uint32_t dst, const void* src) {
    asm volatile("cp.async.cg.shared.global [%0], [%1], 16;"
                 :: "r"(dst), "l"(src));
}

// SMEM layout (bytes). Row stride 272 = 17*16B -> conflict-free ldmatrix.
#define TSTR 272
#define OFF_BIAS 0
#define OFF_AH   1024
#define OFF_AL   (OFF_AH + 64 * TSTR)
#define OFF_BH   (OFF_AL + 64 * TSTR)
#define OFF_BL   (OFF_BH + 256 * TSTR)
#define SMEM_TOTAL (OFF_BL + 256 * TSTR)   // 175104

// ---------------------------------------------------------------------------
// Tensor-core dual GEMM (pre-split bf16 hi/lo inputs, 3xMMA, fp32-class):
//   Yout[m,0:128] = X @ W0^T + b0 ;  Nbuf[m,0:128] = X @ W1^T + b1
// CTA: 64 rows x 256 cols, K=128 resident. 8 warps = 2(M) x 4(N), warp 32x64.
// ---------------------------------------------------------------------------
__global__ __launch_bounds__(256, 1)
void gemm_dual_tc(const __nv_bfloat16* __restrict__ XH,
                  const __nv_bfloat16* __restrict__ XL,
                  const __nv_bfloat16* __restrict__ WH,   // layer base [256][128]
                  const __nv_bfloat16* __restrict__ WL,
                  const float* __restrict__ b0, const float* __restrict__ b1,
                  float* __restrict__ Yout, float* __restrict__ Nbuf)
{
    extern __shared__ char smem[];
    const uint32_t sb = smem_u32(smem);
    const int tid  = threadIdx.x;
    const int wid  = tid >> 5;
    const int lane = tid & 31;
    const int m0   = blockIdx.x * 64;

    // bias into smem
    ((float*)(smem + OFF_BIAS))[tid] = (tid < 128) ? b0[tid] : b1[tid - 128];

    // ---- B tiles via cp.async: 256 rows x 256B each plane ----
#pragma unroll
    for (int i = 0; i < 16; i++) {
        int c = tid + i * 256;
        int n = c >> 4, kc = c & 15;
        uint32_t so = (uint32_t)(n * TSTR + kc * 16);
        const size_t go = ((size_t)n << 7) + kc * 8;
        cp16(sb + OFF_BH + so, WH + go);
        cp16(sb + OFF_BL + so, WL + go);
    }
    // ---- A tiles: 64 rows x 256B each plane ----
#pragma unroll
    for (int i = 0; i < 4; i++) {
        int c = tid + i * 256;
        int r = c >> 4, kc = c & 15;
        int grow = m0 + r;
        uint32_t so = (uint32_t)(r * TSTR + kc * 16);
        if (grow < NV) {
            const size_t go = ((size_t)grow << 7) + kc * 8;
            cp16(sb + OFF_AH + so, XH + go);
            cp16(sb + OFF_AL + so, XL + go);
        } else {
            *(uint4*)(smem + OFF_AH + so) = make_uint4(0, 0, 0, 0);
            *(uint4*)(smem + OFF_AL + so) = make_uint4(0, 0, 0, 0);
        }
    }
    asm volatile("cp.async.commit_group;");
    asm volatile("cp.async.wait_group 0;");
    __syncthreads();

    // ---- warp tiling: wm in {0,1} (rows), wn in {0..3} (cols) ----
    const int wm = wid & 1;
    const int wn = wid >> 1;

    const uint32_t a_row   = (uint32_t)(wm * 32 + (lane & 15));
    const uint32_t a_kh    = (uint32_t)((lane >> 4) * 8);
    const uint32_t a_base  = sb + OFF_AH + a_row * TSTR + a_kh * 2;
    const uint32_t b_n     = (uint32_t)(wn * 64 + (lane & 7) + ((lane >> 4) * 8));
    const uint32_t b_kh    = (uint32_t)(((lane >> 3) & 1) * 8);
    const uint32_t b_base  = sb + OFF_BH + b_n * TSTR + b_kh * 2;

    float acc[2][8][4];
#pragma unroll
    for (int mt = 0; mt < 2; mt++)
#pragma unroll
        for (int nt = 0; nt < 8; nt++)
#pragma unroll
            for (int q = 0; q < 4; q++) acc[mt][nt][q] = 0.f;

#pragma unroll
    for (int s = 0; s < 8; s++) {
        uint32_t Ahf[2][4], Alf[2][4], Bhf[4][4], Blf[4][4];
#pragma unroll
        for (int mt = 0; mt < 2; mt++) {
            uint32_t ad = a_base + (uint32_t)(mt * 16 * TSTR + s * 32);
            ldmatrix_x4(Ahf[mt], ad);
            ldmatrix_x4(Alf[mt], ad + (OFF_AL - OFF_AH));
        }
#pragma unroll
        for (int p = 0; p < 4; p++) {
            uint32_t bd = b_base + (uint32_t)(p * 16 * TSTR + s * 32);
            ldmatrix_x4(Bhf[p], bd);
            ldmatrix_x4(Blf[p], bd + (OFF_BL - OFF_BH));
        }
#pragma unroll
        for (int mt = 0; mt < 2; mt++)
#pragma unroll
            for (int nt = 0; nt < 8; nt++) {
                const uint32_t* bh = &Bhf[nt >> 1][(nt & 1) * 2];
                const uint32_t* bl = &Blf[nt >> 1][(nt & 1) * 2];
                mma16816(acc[mt][nt], Ahf[mt], bh);   // hi*hi
                mma16816(acc[mt][nt], Alf[mt], bh);   // lo*hi
                mma16816(acc[mt][nt], Ahf[mt], bl);   // hi*lo
            }
    }

    // ---- epilogue: bias + guarded float2 stores ----
    const int g = lane >> 2;
    const int t = lane & 3;
    const bool isY = (wn < 2);
    float* dbase = isY ? Yout : Nbuf;
    const float* bs = (const float*)(smem + OFF_BIAS);
#pragma unroll
    for (int mt = 0; mt < 2; mt++) {
        int row0 = m0 + wm * 32 + mt * 16 + g;
#pragma unroll
        for (int nt = 0; nt < 8; nt++) {
            int col = wn * 64 + nt * 8 + t * 2;
            float b0v = bs[col], b1v = bs[col + 1];
            int cc = isY ? col : (col - 128);
            if (row0 < NV) {
                float2 o = make_float2(acc[mt][nt][0] + b0v, acc[mt][nt][1] + b1v);
                *(float2*)(dbase + (size_t)row0 * 128 + cc) = o;
            }
            if (row0 + 8 < NV) {
                float2 o = make_float2(acc[mt][nt][2] + b0v, acc[mt][nt][3] + b1v);
                *(float2*)(dbase + (size_t)(row0 + 8) * 128 + cc) = o;
            }
        }
    }
}

// ---------------------------------------------------------------------------
// CSR build kernels (edges are static; built once per launch)
// ---------------------------------------------------------------------------
__global__ __launch_bounds__(256)
void deg_count(const int2* __restrict__ edges, int* __restrict__ deg)
{
    int t = blockIdx.x * blockDim.x + threadIdx.x;
    if (t >= NE) return;
    int2 e = edges[t];
    atomicAdd(&deg[e.x], 1);
    atomicAdd(&deg[e.y], 1);
}

__global__ __launch_bounds__(1024)
void scan1(const int* __restrict__ deg, int* __restrict__ incl, int* __restrict__ bsum)
{
    __shared__ int ws[32];
    int i = blockIdx.x * 1024 + threadIdx.x;
    int lane = threadIdx.x & 31, wid = threadIdx.x >> 5;
    int x = (i < NV) ? deg[i] : 0;
#pragma unroll
    for (int d = 1; d < 32; d <<= 1) {
        int t = __shfl_up_sync(0xffffffffu, x, d);
        if (lane >= d) x += t;
    }
    if (lane == 31) ws[wid] = x;
    __syncthreads();
    if (wid == 0) {
        int w = ws[lane];
#pragma unroll
        for (int d = 1; d < 32; d <<= 1) {
            int t = __shfl_up_sync(0xffffffffu, w, d);
            if (lane >= d) w += t;
        }
        ws[lane] = w;
    }
    __syncthreads();
    int off = (wid > 0) ? ws[wid - 1] : 0;
    int v = x + off;
    if (i < NV) incl[i] = v;
    if (threadIdx.x == 1023) bsum[blockIdx.x] = v;
}

__global__ void scan2(int* bsum)
{
    if (threadIdx.x == 0 && blockIdx.x == 0) {
        int acc = 0;
        for (int b = 0; b < NB_SCAN; b++) { int t = bsum[b]; bsum[b] = acc; acc += t; }
    }
}

__global__ __launch_bounds__(256)
void scan3(const int* __restrict__ incl, const int* __restrict__ deg,
           const int* __restrict__ bsum, int* __restrict__ indptr,
           int* __restrict__ cursor)
{
    int i = blockIdx.x * blockDim.x + threadIdx.x;
    if (i >= NV) return;
    int total = incl[i] + bsum[i >> 10];
    int ex = total - deg[i];
    indptr[i] = ex;
    cursor[i] = ex;
    if (i == NV - 1) indptr[NV] = total;
}

__global__ __launch_bounds__(256)
void fill_adj(const int2* __restrict__ edges, int* __restrict__ cursor,
              int* __restrict__ adj)
{
    int t = blockIdx.x * blockDim.x + threadIdx.x;
    if (t >= NE) return;
    int2 e = edges[t];
    int p = atomicAdd(&cursor[e.x], 1); adj[p] = e.y;
    int q = atomicAdd(&cursor[e.y], 1); adj[q] = e.x;
}

// ---------------------------------------------------------------------------
// Weight pre-split: all 13 layers' (W0|W1) fp32 -> bf16 hi/lo planes
// ---------------------------------------------------------------------------
__global__ __launch_bounds__(256)
void wsplit(const float* __restrict__ W0_1, const float* __restrict__ W1_1,
            const float* __restrict__ W0_h, const float* __restrict__ W1_h,
            __nv_bfloat16* __restrict__ WH, __nv_bfloat16* __restrict__ WL)
{
    int idx = blockIdx.x * blockDim.x + threadIdx.x;   // float4 units
    if (idx >= 13 * 256 * 32) return;
    int layer = idx / (256 * 32);
    int rem   = idx % (256 * 32);
    int row   = rem >> 5;
    int c4    = (rem & 31) * 4;
    const float* src;
    if (layer == 0)
        src = (row < 128) ? (W0_1 + (size_t)row * 128) : (W1_1 + (size_t)(row - 128) * 128);
    else
        src = (row < 128) ? (W0_h + (size_t)(layer - 1) * 16384 + (size_t)row * 128)
                          : (W1_h + (size_t)(layer - 1) * 16384 + (size_t)(row - 128) * 128);
    float4 v = *(const float4*)(src + c4);
    __nv_bfloat16 h0 = __float2bfloat16_rn(v.x), h1 = __float2bfloat16_rn(v.y);
    __nv_bfloat16 h2 = __float2bfloat16_rn(v.z), h3 = __float2bfloat16_rn(v.w);
    float l0 = v.x - __bfloat162float(h0), l1 = v.y - __bfloat162float(h1);
    float l2 = v.z - __bfloat162float(h2), l3 = v.w - __bfloat162float(h3);
    size_t o = ((size_t)(layer * 256 + row) << 7) + c4;
    *(uint2*)(WH + o) = make_uint2(pk(h0, h1), pk(h2, h3));
    *(uint2*)(WL + o) = make_uint2(pk(__float2bfloat16_rn(l0), __float2bfloat16_rn(l1)),
                                   pk(__float2bfloat16_rn(l2), __float2bfloat16_rn(l3)));
}

// features fp32 -> hi/lo planes (no relu)
__global__ __launch_bounds__(256)
void featsplit(const float4* __restrict__ X, __nv_bfloat16* __restrict__ AH,
               __nv_bfloat16* __restrict__ AL)
{
    int idx = blockIdx.x * blockDim.x + threadIdx.x;   // float4 units
    if (idx >= NV * 32) return;
    float4 v = X[idx];
    __nv_bfloat16 h0 = __float2bfloat16_rn(v.x), h1 = __float2bfloat16_rn(v.y);
    __nv_bfloat16 h2 = __float2bfloat16_rn(v.z), h3 = __float2bfloat16_rn(v.w);
    float l0 = v.x - __bfloat162float(h0), l1 = v.y - __bfloat162float(h1);
    float l2 = v.z - __bfloat162float(h2), l3 = v.w - __bfloat162float(h3);
    *(uint2*)(AH + (size_t)idx * 4) = make_uint2(pk(h0, h1), pk(h2, h3));
    *(uint2*)(AL + (size_t)idx * 4) =
        make_uint2(pk(__float2bfloat16_rn(l0), __float2bfloat16_rn(l1)),
                   pk(__float2bfloat16_rn(l2), __float2bfloat16_rn(l3)));
}

// ---------------------------------------------------------------------------
// CSR gather-aggregate: x = relu(Y[v] + sum_{j in adj(v)} N[j]); emit hi/lo
// planes for the next layer. Warp per vertex, lane = one float4.
// ---------------------------------------------------------------------------
__global__ __launch_bounds__(256)
void agg_csr(const float4* __restrict__ Y, const float4* __restrict__ Nb,
             const int* __restrict__ indptr, const int* __restrict__ adj,
             __nv_bfloat16* __restrict__ AH, __nv_bfloat16* __restrict__ AL)
{
    int w = (blockIdx.x * blockDim.x + threadIdx.x) >> 5;
    int lane = threadIdx.x & 31;
    if (w >= NV) return;
    float4 acc = Y[(size_t)w * 32 + lane];
    int s = indptr[w], e = indptr[w + 1];
    for (int k = s; k < e; k++) {
        int j = adj[k];
        float4 n = Nb[(size_t)j * 32 + lane];
        acc.x += n.x; acc.y += n.y; acc.z += n.z; acc.w += n.w;
    }
    acc.x = fmaxf(acc.x, 0.f); acc.y = fmaxf(acc.y, 0.f);
    acc.z = fmaxf(acc.z, 0.f); acc.w = fmaxf(acc.w, 0.f);
    __nv_bfloat16 h0 = __float2bfloat16_rn(acc.x), h1 = __float2bfloat16_rn(acc.y);
    __nv_bfloat16 h2 = __float2bfloat16_rn(acc.z), h3 = __float2bfloat16_rn(acc.w);
    float l0 = acc.x - __bfloat162float(h0), l1 = acc.y - __bfloat162float(h1);
    float l2 = acc.z - __bfloat162float(h2), l3 = acc.w - __bfloat162float(h3);
    size_t o = ((size_t)w << 7) + lane * 4;
    *(uint2*)(AH + o) = make_uint2(pk(h0, h1), pk(h2, h3));
    *(uint2*)(AL + o) = make_uint2(pk(__float2bfloat16_rn(l0), __float2bfloat16_rn(l1)),
                                   pk(__float2bfloat16_rn(l2), __float2bfloat16_rn(l3)));
}

// ---------------------------------------------------------------------------
// Final layer: z = (Rh+Rl) + (Ah+Al); y = z@W0l^T + b0l; n = z@W1l^T + b1l
// ---------------------------------------------------------------------------
__global__ __launch_bounds__(256)
void final_gemm(const __nv_bfloat16* __restrict__ Rh, const __nv_bfloat16* __restrict__ Rl,
                const __nv_bfloat16* __restrict__ Ahp, const __nv_bfloat16* __restrict__ Alp,
                const float* __restrict__ W0, const float* __restrict__ b0,
                const float* __restrict__ W1, const float* __restrict__ b1,
                float* __restrict__ Yout /*NV*3*/, float* __restrict__ Nl /*NV*3*/)
{
    __shared__ float w[6][128];
    int tid = threadIdx.x;
    for (int i = tid; i < 384; i += blockDim.x) {
        w[i / 128][i % 128]     = W0[i];
        w[3 + i / 128][i % 128] = W1[i];
    }
    __syncthreads();

    int row  = blockIdx.x * (blockDim.x >> 5) + (tid >> 5);
    int lane = tid & 31;
    if (row >= NV) return;

    size_t o = ((size_t)row << 7) + lane * 4;
    uint2 rh = *(const uint2*)(Rh + o), rl = *(const uint2*)(Rl + o);
    uint2 ah = *(const uint2*)(Ahp + o), al = *(const uint2*)(Alp + o);
    float2 a0 = up2(rh.x), a1 = up2(rh.y), b0f = up2(rl.x), b1f = up2(rl.y);
    float2 c0 = up2(ah.x), c1 = up2(ah.y), d0 = up2(al.x), d1 = up2(al.y);
    float4 z;
    z.x = (a0.x + b0f.x) + (c0.x + d0.x);
    z.y = (a0.y + b0f.y) + (c0.y + d0.y);
    z.z = (a1.x + b1f.x) + (c1.x + d1.x);
    z.w = (a1.y + b1f.y) + (c1.y + d1.y);

    float s[6];
#pragma unroll
    for (int oo = 0; oo < 6; oo++) {
        float4 wv = ((const float4*)w[oo])[lane];
        s[oo] = z.x * wv.x + z.y * wv.y + z.z * wv.z + z.w * wv.w;
    }
#pragma unroll
    for (int off = 16; off > 0; off >>= 1)
#pragma unroll
        for (int oo = 0; oo < 6; oo++)
            s[oo] += __shfl_down_sync(0xffffffffu, s[oo], off);

    if (lane == 0) {
#pragma unroll
        for (int oo = 0; oo < 3; oo++) {
            Yout[(size_t)row * 3 + oo] = s[oo] + b0[oo];
            Nl[(size_t)row * 3 + oo]   = s[3 + oo] + b1[oo];
        }
    }
}

// Final scatter over D_OUT=3: one thread per edge, scalar atomics.
__global__ __launch_bounds__(256)
void scatter3(const float* __restrict__ Nl, const int2* __restrict__ edges,
              float* __restrict__ Out)
{
    int t = blockIdx.x * blockDim.x + threadIdx.x;
    if (t >= NE) return;
    int2 e = edges[t];
#pragma unroll
    for (int o = 0; o < 3; o++) {
        atomicAdd(Out + (size_t)e.x * 3 + o, Nl[(size_t)e.y * 3 + o]);
        atomicAdd(Out + (size_t)e.y * 3 + o, Nl[(size_t)e.x * 3 + o]);
    }
}

// auxiliary = hi+lo reconstruction of relu(last hidden output)
__global__ __launch_bounds__(256)
void aux_sum(const __nv_bfloat16* __restrict__ AH, const __nv_bfloat16* __restrict__ AL,
             float4* __restrict__ out)
{
    int idx = blockIdx.x * blockDim.x + threadIdx.x;   // float4 units
    if (idx >= NV * 32) return;
    uint2 h = *(const uint2*)(AH + (size_t)idx * 4);
    uint2 l = *(const uint2*)(AL + (size_t)idx * 4);
    float2 h0 = up2(h.x), h1 = up2(h.y), l0 = up2(l.x), l1 = up2(l.y);
    out[idx] = make_float4(h0.x + l0.x, h0.y + l0.y, h1.x + l1.x, h1.y + l1.y);
}

// ---------------------------------------------------------------------------
extern "C" void kernel_launch(void* const* d_in, const int* in_sizes, int n_in,
                              void* d_out, int out_size)
{
    const float* features = (const float*)d_in[0];
    const int2*  edges    = (const int2*)d_in[1];
    const float* W0_1 = (const float*)d_in[2];
    const float* b0_1 = (const float*)d_in[3];
    const float* W1_1 = (const float*)d_in[4];
    const float* b1_1 = (const float*)d_in[5];
    const float* W0_h = (const float*)d_in[6];
    const float* b0_h = (const float*)d_in[7];
    const float* W1_h = (const float*)d_in[8];
    const float* b1_h = (const float*)d_in[9];
    const float* W0_l = (const float*)d_in[10];
    const float* b0_l = (const float*)d_in[11];
    const float* W1_l = (const float*)d_in[12];
    const float* b1_l = (const float*)d_in[13];
    float* out = (float*)d_out;   // [vertices NV*3 | auxiliary NV*128]

    float *Y, *N, *NL;
    __nv_bfloat16 *Ah, *Al, *Rh, *Rl, *WH, *WL;
    int *deg, *incl, *bsum, *indptr, *cursor, *adj;
    cudaGetSymbolAddress((void**)&Y,  g_Y);
    cudaGetSymbolAddress((void**)&N,  g_N);
    cudaGetSymbolAddress((void**)&NL, g_NL);
    cudaGetSymbolAddress((void**)&Ah, g_Ah);
    cudaGetSymbolAddress((void**)&Al, g_Al);
    cudaGetSymbolAddress((void**)&Rh, g_Rh);
    cudaGetSymbolAddress((void**)&Rl, g_Rl);
    cudaGetSymbolAddress((void**)&WH, g_WH);
    cudaGetSymbolAddress((void**)&WL, g_WL);
    cudaGetSymbolAddress((void**)&deg,    g_deg);
    cudaGetSymbolAddress((void**)&incl,   g_incl);
    cudaGetSymbolAddress((void**)&bsum,   g_bsum);
    cudaGetSymbolAddress((void**)&indptr, g_indptr);
    cudaGetSymbolAddress((void**)&cursor, g_cursor);
    cudaGetSymbolAddress((void**)&adj,    g_adj);

    cudaFuncSetAttribute(gemm_dual_tc,
                         cudaFuncAttributeMaxDynamicSharedMemorySize, SMEM_TOTAL);

    const int gemmBlocks = (NV + 63) / 64;            // 1563
    const int aggBlocks  = (NV * 32 + 255) / 256;     // warp per vertex
    const int edgeBlocks = (NE + 255) / 256;

    // ---- CSR build (edges static; rebuilt each call for determinism) ----
    cudaMemsetAsync(deg, 0, NV * sizeof(int));
    deg_count<<<edgeBlocks, 256>>>(edges, deg);
    scan1<<<NB_SCAN, 1024>>>(deg, incl, bsum);
    scan2<<<1, 32>>>(bsum);
    scan3<<<(NV + 255) / 256, 256>>>(incl, deg, bsum, indptr, cursor);
    fill_adj<<<edgeBlocks, 256>>>(edges, cursor, adj);

    // ---- one-time conversions ----
    wsplit<<<(13 * 256 * 32 + 255) / 256, 256>>>(W0_1, W1_1, W0_h, W1_h, WH, WL);
    featsplit<<<(NV * 32 + 255) / 256, 256>>>((const float4*)features, Ah, Al);

    // ---- layer 1 (in -> hidden) ----
    gemm_dual_tc<<<gemmBlocks, 256, SMEM_TOTAL>>>(Ah, Al, WH, WL, b0_1, b1_1, Y, N);
    agg_csr<<<aggBlocks, 256>>>((const float4*)Y, (const float4*)N, indptr, adj, Rh, Rl);

    // ---- 12 hidden layers ----
    const __nv_bfloat16* ih = Rh;
    const __nv_bfloat16* il = Rl;
    for (int l = 0; l < LHID; l++) {
        gemm_dual_tc<<<gemmBlocks, 256, SMEM_TOTAL>>>(
            ih, il, WH + (size_t)(1 + l) * 256 * 128, WL + (size_t)(1 + l) * 256 * 128,
            b0_h + l * DH, b1_h + l * DH, Y, N);
        agg_csr<<<aggBlocks, 256>>>((const float4*)Y, (const float4*)N, indptr, adj, Ah, Al);
        ih = Ah; il = Al;
    }
    // Ah/Al now hold relu(last hidden output) planes.

    // ---- final layer: z = relu(residual) + relu(x_last) ----
    final_gemm<<<(NV + 7) / 8, 256>>>(Rh, Rl, Ah, Al, W0_l, b0_l, W1_l, b1_l, out, NL);
    scatter3<<<edgeBlocks, 256>>>(NL, edges, out);

    // ---- auxiliary ----
    aux_sum<<<(NV * 32 + 255) / 256, 256>>>(Ah, Al, (float4*)(out + (size_t)NV * 3));
}

// round 5
// speedup vs baseline: 2.1638x; 1.0690x over previous
#include <cuda_runtime.h>
#include <cuda_bf16.h>
#include <cstdint>

#define NV 100000
#define NE 300000
#define DH 128
#define LHID 12
#define NB_SCAN 98   // ceil(NV/1024)

// ---------------- scratch (static device globals; no allocation allowed) ---
__device__ float g_Y[NV * DH];              // self-transform output (fp32)
__device__ float g_N[NV * DH];              // neighbor-transform output (fp32)
__device__ __nv_bfloat16 g_Ah[NV * DH];     // current layer input, hi plane
__device__ __nv_bfloat16 g_Al[NV * DH];     // current layer input, lo plane
__device__ __nv_bfloat16 g_Rh[NV * DH];     // residual (layer-1 out) hi
__device__ __nv_bfloat16 g_Rl[NV * DH];     // residual lo
__device__ __nv_bfloat16 g_WH[13 * 256 * DH];  // pre-split weights hi (W0|W1 per layer)
__device__ __nv_bfloat16 g_WL[13 * 256 * DH];  // pre-split weights lo
__device__ float g_NL[NV * 3];              // final-layer neighbor transform
// CSR build
__device__ int g_deg[NV];
__device__ int g_incl[NV];
__device__ int g_bsum[NB_SCAN];
__device__ int g_indptr[NV + 1];
__device__ int g_cursor[NV];
__device__ int g_adj[2 * NE];

// ======================= helpers ===========================================
__device__ __forceinline__ uint32_t smem_u32(const void* p) {
    uint32_t a;
    asm("{ .reg .u64 t; cvta.to.shared.u64 t, %1; cvt.u32.u64 %0, t; }"
        : "=r"(a) : "l"(p));
    return a;
}
__device__ __forceinline__ void ldmatrix_x4(uint32_t* r, uint32_t addr) {
    asm volatile("ldmatrix.sync.aligned.m8n8.x4.shared.b16 {%0,%1,%2,%3}, [%4];"
                 : "=r"(r[0]), "=r"(r[1]), "=r"(r[2]), "=r"(r[3]) : "r"(addr));
}
__device__ __forceinline__ void mma16816(float* c, const uint32_t* a, const uint32_t* b) {
    asm volatile(
        "mma.sync.aligned.m16n8k16.row.col.f32.bf16.bf16.f32 "
        "{%0,%1,%2,%3}, {%4,%5,%6,%7}, {%8,%9}, {%0,%1,%2,%3};"
        : "+f"(c[0]), "+f"(c[1]), "+f"(c[2]), "+f"(c[3])
        : "r"(a[0]), "r"(a[1]), "r"(a[2]), "r"(a[3]), "r"(b[0]), "r"(b[1]));
}
__device__ __forceinline__ uint32_t pk(__nv_bfloat16 a, __nv_bfloat16 b) {
    uint16_t ua = *(uint16_t*)&a, ub = *(uint16_t*)&b;
    return (uint32_t)ua | ((uint32_t)ub << 16);
}
__device__ __forceinline__ float2 up2(uint32_t p) {
    __nv_bfloat162 b = *reinterpret_cast<__nv_bfloat162*>(&p);
    return make_float2(__bfloat162float(b.x), __bfloat162float(b.y));
}
__device__ __forceinline__ void cp16(uint32_t dst, const void* src) {
    asm volatile("cp.async.cg.shared.global [%0], [%1], 16;"
                 :: "r"(dst), "l"(src));
}

// SMEM layout (bytes). Row stride 272 = 17*16B -> conflict-free ldmatrix.
#define TSTR 272
#define OFF_BIAS 0
#define OFF_AH   1024
#define OFF_AL   (OFF_AH + 128 * TSTR)     // 35840
#define OFF_BH   (OFF_AL + 128 * TSTR)     // 70656
#define OFF_BL   (OFF_BH + 256 * TSTR)     // 140288
#define SMEM_TOTAL (OFF_BL + 256 * TSTR)   // 209920

// ---------------------------------------------------------------------------
// Tensor-core dual GEMM (pre-split bf16 hi/lo inputs, 3xMMA, fp32-class):
//   Yout[m,0:128] = X @ W0^T + b0 ;  Nbuf[m,0:128] = X @ W1^T + b1
// CTA: 128 rows x 256 cols, K=128 resident. 8 warps = 2(M) x 4(N), warp 64x64.
// ---------------------------------------------------------------------------
__global__ __launch_bounds__(256, 1)
void gemm_dual_tc(const __nv_bfloat16* __restrict__ XH,
                  const __nv_bfloat16* __restrict__ XL,
                  const __nv_bfloat16* __restrict__ WH,   // layer base [256][128]
                  const __nv_bfloat16* __restrict__ WL,
                  const float* __restrict__ b0, const float* __restrict__ b1,
                  float* __restrict__ Yout, float* __restrict__ Nbuf)
{
    extern __shared__ char smem[];
    const uint32_t sb = smem_u32(smem);
    const int tid  = threadIdx.x;
    const int wid  = tid >> 5;
    const int lane = tid & 31;
    const int m0   = blockIdx.x * 128;

    // bias into smem
    ((float*)(smem + OFF_BIAS))[tid] = (tid < 128) ? b0[tid] : b1[tid - 128];

    // ---- B tiles via cp.async: 256 rows x 256B each plane ----
#pragma unroll
    for (int i = 0; i < 16; i++) {
        int c = tid + i * 256;
        int n = c >> 4, kc = c & 15;
        uint32_t so = (uint32_t)(n * TSTR + kc * 16);
        const size_t go = ((size_t)n << 7) + kc * 8;
        cp16(sb + OFF_BH + so, WH + go);
        cp16(sb + OFF_BL + so, WL + go);
    }
    // ---- A tiles: 128 rows x 256B each plane ----
#pragma unroll
    for (int i = 0; i < 8; i++) {
        int c = tid + i * 256;
        int r = c >> 4, kc = c & 15;
        int grow = m0 + r;
        uint32_t so = (uint32_t)(r * TSTR + kc * 16);
        if (grow < NV) {
            const size_t go = ((size_t)grow << 7) + kc * 8;
            cp16(sb + OFF_AH + so, XH + go);
            cp16(sb + OFF_AL + so, XL + go);
        } else {
            *(uint4*)(smem + OFF_AH + so) = make_uint4(0, 0, 0, 0);
            *(uint4*)(smem + OFF_AL + so) = make_uint4(0, 0, 0, 0);
        }
    }
    asm volatile("cp.async.commit_group;");
    asm volatile("cp.async.wait_group 0;");
    __syncthreads();

    // ---- warp tiling: wm in {0,1} (64-row bands), wn in {0..3} (64-col) ----
    const int wm = wid & 1;
    const int wn = wid >> 1;

    const uint32_t a_row   = (uint32_t)(wm * 64 + (lane & 15));
    const uint32_t a_kh    = (uint32_t)((lane >> 4) * 8);
    const uint32_t a_base  = sb + OFF_AH + a_row * TSTR + a_kh * 2;
    const uint32_t b_n     = (uint32_t)(wn * 64 + (lane & 7) + ((lane >> 4) * 8));
    const uint32_t b_kh    = (uint32_t)(((lane >> 3) & 1) * 8);
    const uint32_t b_base  = sb + OFF_BH + b_n * TSTR + b_kh * 2;

    float acc[4][8][4];
#pragma unroll
    for (int mt = 0; mt < 4; mt++)
#pragma unroll
        for (int nt = 0; nt < 8; nt++)
#pragma unroll
            for (int q = 0; q < 4; q++) acc[mt][nt][q] = 0.f;

#pragma unroll
    for (int s = 0; s < 8; s++) {
        uint32_t Ahf[4][4], Alf[4][4], Bhf[4][4], Blf[4][4];
#pragma unroll
        for (int mt = 0; mt < 4; mt++) {
            uint32_t ad = a_base + (uint32_t)(mt * 16 * TSTR + s * 32);
            ldmatrix_x4(Ahf[mt], ad);
            ldmatrix_x4(Alf[mt], ad + (OFF_AL - OFF_AH));
        }
#pragma unroll
        for (int p = 0; p < 4; p++) {
            uint32_t bd = b_base + (uint32_t)(p * 16 * TSTR + s * 32);
            ldmatrix_x4(Bhf[p], bd);
            ldmatrix_x4(Blf[p], bd + (OFF_BL - OFF_BH));
        }
#pragma unroll
        for (int mt = 0; mt < 4; mt++)
#pragma unroll
            for (int nt = 0; nt < 8; nt++) {
                const uint32_t* bh = &Bhf[nt >> 1][(nt & 1) * 2];
                const uint32_t* bl = &Blf[nt >> 1][(nt & 1) * 2];
                mma16816(acc[mt][nt], Ahf[mt], bh);   // hi*hi
                mma16816(acc[mt][nt], Alf[mt], bh);   // lo*hi
                mma16816(acc[mt][nt], Ahf[mt], bl);   // hi*lo
            }
    }

    // ---- epilogue: bias + guarded float2 stores ----
    const int g = lane >> 2;
    const int t = lane & 3;
    const bool isY = (wn < 2);
    float* dbase = isY ? Yout : Nbuf;
    const float* bs = (const float*)(smem + OFF_BIAS);
#pragma unroll
    for (int mt = 0; mt < 4; mt++) {
        int row0 = m0 + wm * 64 + mt * 16 + g;
#pragma unroll
        for (int nt = 0; nt < 8; nt++) {
            int col = wn * 64 + nt * 8 + t * 2;
            float b0v = bs[col], b1v = bs[col + 1];
            int cc = isY ? col : (col - 128);
            if (row0 < NV) {
                float2 o = make_float2(acc[mt][nt][0] + b0v, acc[mt][nt][1] + b1v);
                *(float2*)(dbase + (size_t)row0 * 128 + cc) = o;
            }
            if (row0 + 8 < NV) {
                float2 o = make_float2(acc[mt][nt][2] + b0v, acc[mt][nt][3] + b1v);
                *(float2*)(dbase + (size_t)(row0 + 8) * 128 + cc) = o;
            }
        }
    }
}

// ---------------------------------------------------------------------------
// CSR build kernels (edges are static; built once per launch)
// ---------------------------------------------------------------------------
__global__ __launch_bounds__(256)
void deg_count(const int2* __restrict__ edges, int* __restrict__ deg)
{
    int t = blockIdx.x * blockDim.x + threadIdx.x;
    if (t >= NE) return;
    int2 e = edges[t];
    atomicAdd(&deg[e.x], 1);
    atomicAdd(&deg[e.y], 1);
}

__global__ __launch_bounds__(1024)
void scan1(const int* __restrict__ deg, int* __restrict__ incl, int* __restrict__ bsum)
{
    __shared__ int ws[32];
    int i = blockIdx.x * 1024 + threadIdx.x;
    int lane = threadIdx.x & 31, wid = threadIdx.x >> 5;
    int x = (i < NV) ? deg[i] : 0;
#pragma unroll
    for (int d = 1; d < 32; d <<= 1) {
        int t = __shfl_up_sync(0xffffffffu, x, d);
        if (lane >= d) x += t;
    }
    if (lane == 31) ws[wid] = x;
    __syncthreads();
    if (wid == 0) {
        int w = ws[lane];
#pragma unroll
        for (int d = 1; d < 32; d <<= 1) {
            int t = __shfl_up_sync(0xffffffffu, w, d);
            if (lane >= d) w += t;
        }
        ws[lane] = w;
    }
    __syncthreads();
    int off = (wid > 0) ? ws[wid - 1] : 0;
    int v = x + off;
    if (i < NV) incl[i] = v;
    if (threadIdx.x == 1023) bsum[blockIdx.x] = v;
}

__global__ void scan2(int* bsum)
{
    if (threadIdx.x == 0 && blockIdx.x == 0) {
        int acc = 0;
        for (int b = 0; b < NB_SCAN; b++) { int t = bsum[b]; bsum[b] = acc; acc += t; }
    }
}

__global__ __launch_bounds__(256)
void scan3(const int* __restrict__ incl, const int* __restrict__ deg,
           const int* __restrict__ bsum, int* __restrict__ indptr,
           int* __restrict__ cursor)
{
    int i = blockIdx.x * blockDim.x + threadIdx.x;
    if (i >= NV) return;
    int total = incl[i] + bsum[i >> 10];
    int ex = total - deg[i];
    indptr[i] = ex;
    cursor[i] = ex;
    if (i == NV - 1) indptr[NV] = total;
}

__global__ __launch_bounds__(256)
void fill_adj(const int2* __restrict__ edges, int* __restrict__ cursor,
              int* __restrict__ adj)
{
    int t = blockIdx.x * blockDim.x + threadIdx.x;
    if (t >= NE) return;
    int2 e = edges[t];
    int p = atomicAdd(&cursor[e.x], 1); adj[p] = e.y;
    int q = atomicAdd(&cursor[e.y], 1); adj[q] = e.x;
}

// ---------------------------------------------------------------------------
// Weight pre-split: all 13 layers' (W0|W1) fp32 -> bf16 hi/lo planes
// ---------------------------------------------------------------------------
__global__ __launch_bounds__(256)
void wsplit(const float* __restrict__ W0_1, const float* __restrict__ W1_1,
            const float* __restrict__ W0_h, const float* __restrict__ W1_h,
            __nv_bfloat16* __restrict__ WH, __nv_bfloat16* __restrict__ WL)
{
    int idx = blockIdx.x * blockDim.x + threadIdx.x;   // float4 units
    if (idx >= 13 * 256 * 32) return;
    int layer = idx / (256 * 32);
    int rem   = idx % (256 * 32);
    int row   = rem >> 5;
    int c4    = (rem & 31) * 4;
    const float* src;
    if (layer == 0)
        src = (row < 128) ? (W0_1 + (size_t)row * 128) : (W1_1 + (size_t)(row - 128) * 128);
    else
        src = (row < 128) ? (W0_h + (size_t)(layer - 1) * 16384 + (size_t)row * 128)
                          : (W1_h + (size_t)(layer - 1) * 16384 + (size_t)(row - 128) * 128);
    float4 v = *(const float4*)(src + c4);
    __nv_bfloat16 h0 = __float2bfloat16_rn(v.x), h1 = __float2bfloat16_rn(v.y);
    __nv_bfloat16 h2 = __float2bfloat16_rn(v.z), h3 = __float2bfloat16_rn(v.w);
    float l0 = v.x - __bfloat162float(h0), l1 = v.y - __bfloat162float(h1);
    float l2 = v.z - __bfloat162float(h2), l3 = v.w - __bfloat162float(h3);
    size_t o = ((size_t)(layer * 256 + row) << 7) + c4;
    *(uint2*)(WH + o) = make_uint2(pk(h0, h1), pk(h2, h3));
    *(uint2*)(WL + o) = make_uint2(pk(__float2bfloat16_rn(l0), __float2bfloat16_rn(l1)),
                                   pk(__float2bfloat16_rn(l2), __float2bfloat16_rn(l3)));
}

// features fp32 -> hi/lo planes (no relu)
__global__ __launch_bounds__(256)
void featsplit(const float4* __restrict__ X, __nv_bfloat16* __restrict__ AH,
               __nv_bfloat16* __restrict__ AL)
{
    int idx = blockIdx.x * blockDim.x + threadIdx.x;   // float4 units
    if (idx >= NV * 32) return;
    float4 v = X[idx];
    __nv_bfloat16 h0 = __float2bfloat16_rn(v.x), h1 = __float2bfloat16_rn(v.y);
    __nv_bfloat16 h2 = __float2bfloat16_rn(v.z), h3 = __float2bfloat16_rn(v.w);
    float l0 = v.x - __bfloat162float(h0), l1 = v.y - __bfloat162float(h1);
    float l2 = v.z - __bfloat162float(h2), l3 = v.w - __bfloat162float(h3);
    *(uint2*)(AH + (size_t)idx * 4) = make_uint2(pk(h0, h1), pk(h2, h3));
    *(uint2*)(AL + (size_t)idx * 4) =
        make_uint2(pk(__float2bfloat16_rn(l0), __float2bfloat16_rn(l1)),
                   pk(__float2bfloat16_rn(l2), __float2bfloat16_rn(l3)));
}

// ---------------------------------------------------------------------------
// CSR gather-aggregate: x = relu(Y[v] + sum_{j in adj(v)} N[j]); emit hi/lo
// planes for the next layer. Warp per vertex, lane = one float4.
// ---------------------------------------------------------------------------
__global__ __launch_bounds__(256)
void agg_csr(const float4* __restrict__ Y, const float4* __restrict__ Nb,
             const int* __restrict__ indptr, const int* __restrict__ adj,
             __nv_bfloat16* __restrict__ AH, __nv_bfloat16* __restrict__ AL)
{
    int w = (blockIdx.x * blockDim.x + threadIdx.x) >> 5;
    int lane = threadIdx.x & 31;
    if (w >= NV) return;
    float4 acc = Y[(size_t)w * 32 + lane];
    int s = indptr[w], e = indptr[w + 1];
    for (int k = s; k < e; k++) {
        int j = adj[k];
        float4 n = Nb[(size_t)j * 32 + lane];
        acc.x += n.x; acc.y += n.y; acc.z += n.z; acc.w += n.w;
    }
    acc.x = fmaxf(acc.x, 0.f); acc.y = fmaxf(acc.y, 0.f);
    acc.z = fmaxf(acc.z, 0.f); acc.w = fmaxf(acc.w, 0.f);
    __nv_bfloat16 h0 = __float2bfloat16_rn(acc.x), h1 = __float2bfloat16_rn(acc.y);
    __nv_bfloat16 h2 = __float2bfloat16_rn(acc.z), h3 = __float2bfloat16_rn(acc.w);
    float l0 = acc.x - __bfloat162float(h0), l1 = acc.y - __bfloat162float(h1);
    float l2 = acc.z - __bfloat162float(h2), l3 = acc.w - __bfloat162float(h3);
    size_t o = ((size_t)w << 7) + lane * 4;
    *(uint2*)(AH + o) = make_uint2(pk(h0, h1), pk(h2, h3));
    *(uint2*)(AL + o) = make_uint2(pk(__float2bfloat16_rn(l0), __float2bfloat16_rn(l1)),
                                   pk(__float2bfloat16_rn(l2), __float2bfloat16_rn(l3)));
}

// ---------------------------------------------------------------------------
// Final layer: z = (Rh+Rl) + (Ah+Al); y = z@W0l^T + b0l; n = z@W1l^T + b1l
// ---------------------------------------------------------------------------
__global__ __launch_bounds__(256)
void final_gemm(const __nv_bfloat16* __restrict__ Rh, const __nv_bfloat16* __restrict__ Rl,
                const __nv_bfloat16* __restrict__ Ahp, const __nv_bfloat16* __restrict__ Alp,
                const float* __restrict__ W0, const float* __restrict__ b0,
                const float* __restrict__ W1, const float* __restrict__ b1,
                float* __restrict__ Yout /*NV*3*/, float* __restrict__ Nl /*NV*3*/)
{
    __shared__ float w[6][128];
    int tid = threadIdx.x;
    for (int i = tid; i < 384; i += blockDim.x) {
        w[i / 128][i % 128]     = W0[i];
        w[3 + i / 128][i % 128] = W1[i];
    }
    __syncthreads();

    int row  = blockIdx.x * (blockDim.x >> 5) + (tid >> 5);
    int lane = tid & 31;
    if (row >= NV) return;

    size_t o = ((size_t)row << 7) + lane * 4;
    uint2 rh = *(const uint2*)(Rh + o), rl = *(const uint2*)(Rl + o);
    uint2 ah = *(const uint2*)(Ahp + o), al = *(const uint2*)(Alp + o);
    float2 a0 = up2(rh.x), a1 = up2(rh.y), b0f = up2(rl.x), b1f = up2(rl.y);
    float2 c0 = up2(ah.x), c1 = up2(ah.y), d0 = up2(al.x), d1 = up2(al.y);
    float4 z;
    z.x = (a0.x + b0f.x) + (c0.x + d0.x);
    z.y = (a0.y + b0f.y) + (c0.y + d0.y);
    z.z = (a1.x + b1f.x) + (c1.x + d1.x);
    z.w = (a1.y + b1f.y) + (c1.y + d1.y);

    float s[6];
#pragma unroll
    for (int oo = 0; oo < 6; oo++) {
        float4 wv = ((const float4*)w[oo])[lane];
        s[oo] = z.x * wv.x + z.y * wv.y + z.z * wv.z + z.w * wv.w;
    }
#pragma unroll
    for (int off = 16; off > 0; off >>= 1)
#pragma unroll
        for (int oo = 0; oo < 6; oo++)
            s[oo] += __shfl_down_sync(0xffffffffu, s[oo], off);

    if (lane == 0) {
#pragma unroll
        for (int oo = 0; oo < 3; oo++) {
            Yout[(size_t)row * 3 + oo] = s[oo] + b0[oo];
            Nl[(size_t)row * 3 + oo]   = s[3 + oo] + b1[oo];
        }
    }
}

// Final scatter over D_OUT=3: one thread per edge, scalar atomics.
__global__ __launch_bounds__(256)
void scatter3(const float* __restrict__ Nl, const int2* __restrict__ edges,
              float* __restrict__ Out)
{
    int t = blockIdx.x * blockDim.x + threadIdx.x;
    if (t >= NE) return;
    int2 e = edges[t];
#pragma unroll
    for (int o = 0; o < 3; o++) {
        atomicAdd(Out + (size_t)e.x * 3 + o, Nl[(size_t)e.y * 3 + o]);
        atomicAdd(Out + (size_t)e.y * 3 + o, Nl[(size_t)e.x * 3 + o]);
    }
}

// auxiliary = hi+lo reconstruction of relu(last hidden output)
__global__ __launch_bounds__(256)
void aux_sum(const __nv_bfloat16* __restrict__ AH, const __nv_bfloat16* __restrict__ AL,
             float4* __restrict__ out)
{
    int idx = blockIdx.x * blockDim.x + threadIdx.x;   // float4 units
    if (idx >= NV * 32) return;
    uint2 h = *(const uint2*)(AH + (size_t)idx * 4);
    uint2 l = *(const uint2*)(AL + (size_t)idx * 4);
    float2 h0 = up2(h.x), h1 = up2(h.y), l0 = up2(l.x), l1 = up2(l.y);
    out[idx] = make_float4(h0.x + l0.x, h0.y + l0.y, h1.x + l1.x, h1.y + l1.y);
}

// ---------------------------------------------------------------------------
extern "C" void kernel_launch(void* const* d_in, const int* in_sizes, int n_in,
                              void* d_out, int out_size)
{
    const float* features = (const float*)d_in[0];
    const int2*  edges    = (const int2*)d_in[1];
    const float* W0_1 = (const float*)d_in[2];
    const float* b0_1 = (const float*)d_in[3];
    const float* W1_1 = (const float*)d_in[4];
    const float* b1_1 = (const float*)d_in[5];
    const float* W0_h = (const float*)d_in[6];
    const float* b0_h = (const float*)d_in[7];
    const float* W1_h = (const float*)d_in[8];
    const float* b1_h = (const float*)d_in[9];
    const float* W0_l = (const float*)d_in[10];
    const float* b0_l = (const float*)d_in[11];
    const float* W1_l = (const float*)d_in[12];
    const float* b1_l = (const float*)d_in[13];
    float* out = (float*)d_out;   // [vertices NV*3 | auxiliary NV*128]

    float *Y, *N, *NL;
    __nv_bfloat16 *Ah, *Al, *Rh, *Rl, *WH, *WL;
    int *deg, *incl, *bsum, *indptr, *cursor, *adj;
    cudaGetSymbolAddress((void**)&Y,  g_Y);
    cudaGetSymbolAddress((void**)&N,  g_N);
    cudaGetSymbolAddress((void**)&NL, g_NL);
    cudaGetSymbolAddress((void**)&Ah, g_Ah);
    cudaGetSymbolAddress((void**)&Al, g_Al);
    cudaGetSymbolAddress((void**)&Rh, g_Rh);
    cudaGetSymbolAddress((void**)&Rl, g_Rl);
    cudaGetSymbolAddress((void**)&WH, g_WH);
    cudaGetSymbolAddress((void**)&WL, g_WL);
    cudaGetSymbolAddress((void**)&deg,    g_deg);
    cudaGetSymbolAddress((void**)&incl,   g_incl);
    cudaGetSymbolAddress((void**)&bsum,   g_bsum);
    cudaGetSymbolAddress((void**)&indptr, g_indptr);
    cudaGetSymbolAddress((void**)&cursor, g_cursor);
    cudaGetSymbolAddress((void**)&adj,    g_adj);

    cudaFuncSetAttribute(gemm_dual_tc,
                         cudaFuncAttributeMaxDynamicSharedMemorySize, SMEM_TOTAL);

    const int gemmBlocks = (NV + 127) / 128;          // 782
    const int aggBlocks  = (NV * 32 + 255) / 256;     // warp per vertex
    const int edgeBlocks = (NE + 255) / 256;

    // ---- CSR build (edges static; rebuilt each call for determinism) ----
    cudaMemsetAsync(deg, 0, NV * sizeof(int));
    deg_count<<<edgeBlocks, 256>>>(edges, deg);
    scan1<<<NB_SCAN, 1024>>>(deg, incl, bsum);
    scan2<<<1, 32>>>(bsum);
    scan3<<<(NV + 255) / 256, 256>>>(incl, deg, bsum, indptr, cursor);
    fill_adj<<<edgeBlocks, 256>>>(edges, cursor, adj);

    // ---- one-time conversions ----
    wsplit<<<(13 * 256 * 32 + 255) / 256, 256>>>(W0_1, W1_1, W0_h, W1_h, WH, WL);
    featsplit<<<(NV * 32 + 255) / 256, 256>>>((const float4*)features, Ah, Al);

    // ---- layer 1 (in -> hidden) ----
    gemm_dual_tc<<<gemmBlocks, 256, SMEM_TOTAL>>>(Ah, Al, WH, WL, b0_1, b1_1, Y, N);
    agg_csr<<<aggBlocks, 256>>>((const float4*)Y, (const float4*)N, indptr, adj, Rh, Rl);

    // ---- 12 hidden layers ----
    const __nv_bfloat16* ih = Rh;
    const __nv_bfloat16* il = Rl;
    for (int l = 0; l < LHID; l++) {
        gemm_dual_tc<<<gemmBlocks, 256, SMEM_TOTAL>>>(
            ih, il, WH + (size_t)(1 + l) * 256 * 128, WL + (size_t)(1 + l) * 256 * 128,
            b0_h + l * DH, b1_h + l * DH, Y, N);
        agg_csr<<<aggBlocks, 256>>>((const float4*)Y, (const float4*)N, indptr, adj, Ah, Al);
        ih = Ah; il = Al;
    }
    // Ah/Al now hold relu(last hidden output) planes.

    // ---- final layer: z = relu(residual) + relu(x_last) ----
    final_gemm<<<(NV + 7) / 8, 256>>>(Rh, Rl, Ah, Al, W0_l, b0_l, W1_l, b1_l, out, NL);
    scatter3<<<edgeBlocks, 256>>>(NL, edges, out);

    // ---- auxiliary ----
    aux_sum<<<(NV * 32 + 255) / 256, 256>>>(Ah, Al, (float4*)(out + (size_t)NV * 3));
}

// round 6
// speedup vs baseline: 2.6192x; 1.2105x over previous
#include <cuda_runtime.h>
#include <cuda_bf16.h>
#include <cstdint>

#define NV 100000
#define NE 300000
#define DH 128
#define LHID 12
#define NB_SCAN 98   // ceil(NV/1024)
#define NT64 1563    // ceil(NV/64) A-tiles

// ---------------- scratch (static device globals; no allocation allowed) ---
__device__ float g_Y[NV * DH];              // self-transform output (fp32)
__device__ float g_N[NV * DH];              // neighbor-transform output (fp32)
__device__ __nv_bfloat16 g_Ah[NV * DH];     // current layer input, hi plane
__device__ __nv_bfloat16 g_Al[NV * DH];     // current layer input, lo plane
__device__ __nv_bfloat16 g_Rh[NV * DH];     // residual (layer-1 out) hi
__device__ __nv_bfloat16 g_Rl[NV * DH];     // residual lo
__device__ __nv_bfloat16 g_WH[13 * 256 * DH];  // pre-split weights hi (W0|W1 per layer)
__device__ __nv_bfloat16 g_WL[13 * 256 * DH];  // pre-split weights lo
__device__ float g_NL[NV * 3];              // final-layer neighbor transform
// CSR build
__device__ int g_deg[NV];
__device__ int g_incl[NV];
__device__ int g_bsum[NB_SCAN];
__device__ int g_indptr[NV + 1];
__device__ int g_cursor[NV];
__device__ int g_adj[2 * NE];

// ======================= helpers ===========================================
__device__ __forceinline__ uint32_t smem_u32(const void* p) {
    uint32_t a;
    asm("{ .reg .u64 t; cvta.to.shared.u64 t, %1; cvt.u32.u64 %0, t; }"
        : "=r"(a) : "l"(p));
    return a;
}
__device__ __forceinline__ void ldmatrix_x4(uint32_t* r, uint32_t addr) {
    asm volatile("ldmatrix.sync.aligned.m8n8.x4.shared.b16 {%0,%1,%2,%3}, [%4];"
                 : "=r"(r[0]), "=r"(r[1]), "=r"(r[2]), "=r"(r[3]) : "r"(addr));
}
__device__ __forceinline__ void mma16816(float* c, const uint32_t* a, const uint32_t* b) {
    asm volatile(
        "mma.sync.aligned.m16n8k16.row.col.f32.bf16.bf16.f32 "
        "{%0,%1,%2,%3}, {%4,%5,%6,%7}, {%8,%9}, {%0,%1,%2,%3};"
        : "+f"(c[0]), "+f"(c[1]), "+f"(c[2]), "+f"(c[3])
        : "r"(a[0]), "r"(a[1]), "r"(a[2]), "r"(a[3]), "r"(b[0]), "r"(b[1]));
}
__device__ __forceinline__ uint32_t pk(__nv_bfloat16 a, __nv_bfloat16 b) {
    uint16_t ua = *(uint16_t*)&a, ub = *(uint16_t*)&b;
    return (uint32_t)ua | ((uint32_t)ub << 16);
}
__device__ __forceinline__ float2 up2(uint32_t p) {
    __nv_bfloat162 b = *reinterpret_cast<__nv_bfloat162*>(&p);
    return make_float2(__bfloat162float(b.x), __bfloat162float(b.y));
}
__device__ __forceinline__ void cp16(uint32_t dst, const void* src) {
    asm volatile("cp.async.cg.shared.global [%0], [%1], 16;"
                 :: "r"(dst), "l"(src));
}

// SMEM layout (bytes). Row stride 272 = 17*16B -> conflict-free ldmatrix.
#define TSTR 272
#define OFF_BIAS 0
#define OFF_A0   1024
#define A_PLANE  17408                      // 64*272 per plane
#define A_BUF    34816                      // hi+lo
#define OFF_A1   (OFF_A0 + A_BUF)           // 35840
#define OFF_BH   (OFF_A1 + A_BUF)           // 70656
#define OFF_BL   (OFF_BH + 256 * TSTR)      // 140288
#define SMEM_TOTAL (OFF_BL + 256 * TSTR)    // 209920

// ---------------------------------------------------------------------------
// Persistent, pipelined tensor-core dual GEMM (split-bf16, 3xMMA, fp32-class):
//   Yout[m,0:128] = X @ W0^T + b0 ;  Nbuf[m,0:128] = X @ W1^T + b1
// Grid = #SM CTAs. Each CTA: load B (weights) ONCE, then loop over 64-row
// A-tiles with stride gridDim, double-buffered cp.async A prefetch.
// 8 warps = 2(M) x 4(N), warp 32x64.
// ---------------------------------------------------------------------------
__global__ __launch_bounds__(256, 1)
void gemm_dual_tc(const __nv_bfloat16* __restrict__ XH,
                  const __nv_bfloat16* __restrict__ XL,
                  const __nv_bfloat16* __restrict__ WH,   // layer base [256][128]
                  const __nv_bfloat16* __restrict__ WL,
                  const float* __restrict__ b0, const float* __restrict__ b1,
                  float* __restrict__ Yout, float* __restrict__ Nbuf)
{
    extern __shared__ char smem[];
    const uint32_t sb = smem_u32(smem);
    const int tid  = threadIdx.x;
    const int wid  = tid >> 5;
    const int lane = tid & 31;

    // bias into smem
    ((float*)(smem + OFF_BIAS))[tid] = (tid < 128) ? b0[tid] : b1[tid - 128];

    // ---- B tiles via cp.async (once per layer per CTA) ----
#pragma unroll
    for (int i = 0; i < 16; i++) {
        int c = tid + i * 256;
        int n = c >> 4, kc = c & 15;
        uint32_t so = (uint32_t)(n * TSTR + kc * 16);
        const size_t go = ((size_t)n << 7) + kc * 8;
        cp16(sb + OFF_BH + so, WH + go);
        cp16(sb + OFF_BL + so, WL + go);
    }

    // A-tile issue helper (64 rows x 256B per plane)
    auto issueA = [&](int t, int buf) {
        const uint32_t abase = sb + (buf ? OFF_A1 : OFF_A0);
        char* abasep = smem + (buf ? OFF_A1 : OFF_A0);
        const int m0 = t * 64;
#pragma unroll
        for (int i = 0; i < 4; i++) {
            int c = tid + i * 256;
            int r = c >> 4, kc = c & 15;
            int grow = m0 + r;
            uint32_t so = (uint32_t)(r * TSTR + kc * 16);
            if (grow < NV) {
                const size_t go = ((size_t)grow << 7) + kc * 8;
                cp16(abase + so, XH + go);
                cp16(abase + A_PLANE + so, XL + go);
            } else {
                *(uint4*)(abasep + so) = make_uint4(0, 0, 0, 0);
                *(uint4*)(abasep + A_PLANE + so) = make_uint4(0, 0, 0, 0);
            }
        }
    };

    int t = blockIdx.x;
    if (t >= NT64) return;
    issueA(t, 0);
    asm volatile("cp.async.commit_group;");

    // warp tiling constants
    const int wm = wid & 1;
    const int wn = wid >> 1;
    const uint32_t a_roff = (uint32_t)((wm * 32 + (lane & 15)) * TSTR + ((lane >> 4) * 8) * 2);
    const uint32_t b_n    = (uint32_t)(wn * 64 + (lane & 7) + ((lane >> 4) * 8));
    const uint32_t b_kh   = (uint32_t)(((lane >> 3) & 1) * 8);
    const uint32_t b_base = sb + OFF_BH + b_n * TSTR + b_kh * 2;
    const int g = lane >> 2;
    const int tq = lane & 3;
    const bool isY = (wn < 2);
    float* dbase = isY ? Yout : Nbuf;
    const float* bs = (const float*)(smem + OFF_BIAS);

    int p = 0;
    while (t < NT64) {
        const int tn = t + gridDim.x;
        if (tn < NT64) {
            issueA(tn, p ^ 1);
            asm volatile("cp.async.commit_group;");
            asm volatile("cp.async.wait_group 1;");
        } else {
            asm volatile("cp.async.wait_group 0;");
        }
        __syncthreads();

        const uint32_t a_base = sb + (p ? OFF_A1 : OFF_A0) + a_roff;

        float acc[2][8][4];
#pragma unroll
        for (int mt = 0; mt < 2; mt++)
#pragma unroll
            for (int nt = 0; nt < 8; nt++)
#pragma unroll
                for (int q = 0; q < 4; q++) acc[mt][nt][q] = 0.f;

#pragma unroll
        for (int s = 0; s < 8; s++) {
            uint32_t Ahf[2][4], Alf[2][4], Bhf[4][4], Blf[4][4];
#pragma unroll
            for (int mt = 0; mt < 2; mt++) {
                uint32_t ad = a_base + (uint32_t)(mt * 16 * TSTR + s * 32);
                ldmatrix_x4(Ahf[mt], ad);
                ldmatrix_x4(Alf[mt], ad + A_PLANE);
            }
#pragma unroll
            for (int q = 0; q < 4; q++) {
                uint32_t bd = b_base + (uint32_t)(q * 16 * TSTR + s * 32);
                ldmatrix_x4(Bhf[q], bd);
                ldmatrix_x4(Blf[q], bd + (OFF_BL - OFF_BH));
            }
#pragma unroll
            for (int mt = 0; mt < 2; mt++)
#pragma unroll
                for (int nt = 0; nt < 8; nt++) {
                    const uint32_t* bh = &Bhf[nt >> 1][(nt & 1) * 2];
                    const uint32_t* bl = &Blf[nt >> 1][(nt & 1) * 2];
                    mma16816(acc[mt][nt], Ahf[mt], bh);   // hi*hi
                    mma16816(acc[mt][nt], Alf[mt], bh);   // lo*hi
                    mma16816(acc[mt][nt], Ahf[mt], bl);   // hi*lo
                }
        }

        // ---- epilogue: bias + guarded float2 stores ----
        const int m0 = t * 64;
#pragma unroll
        for (int mt = 0; mt < 2; mt++) {
            int row0 = m0 + wm * 32 + mt * 16 + g;
#pragma unroll
            for (int nt = 0; nt < 8; nt++) {
                int col = wn * 64 + nt * 8 + tq * 2;
                float b0v = bs[col], b1v = bs[col + 1];
                int cc = isY ? col : (col - 128);
                if (row0 < NV) {
                    float2 o = make_float2(acc[mt][nt][0] + b0v, acc[mt][nt][1] + b1v);
                    *(float2*)(dbase + (size_t)row0 * 128 + cc) = o;
                }
                if (row0 + 8 < NV) {
                    float2 o = make_float2(acc[mt][nt][2] + b0v, acc[mt][nt][3] + b1v);
                    *(float2*)(dbase + (size_t)(row0 + 8) * 128 + cc) = o;
                }
            }
        }
        __syncthreads();   // protect buf p before next prefetch overwrites it
        t = tn;
        p ^= 1;
    }
}

// ---------------------------------------------------------------------------
// CSR build kernels (edges are static; built once per launch)
// ---------------------------------------------------------------------------
__global__ __launch_bounds__(256)
void deg_count(const int2* __restrict__ edges, int* __restrict__ deg)
{
    int t = blockIdx.x * blockDim.x + threadIdx.x;
    if (t >= NE) return;
    int2 e = edges[t];
    atomicAdd(&deg[e.x], 1);
    atomicAdd(&deg[e.y], 1);
}

__global__ __launch_bounds__(1024)
void scan1(const int* __restrict__ deg, int* __restrict__ incl, int* __restrict__ bsum)
{
    __shared__ int ws[32];
    int i = blockIdx.x * 1024 + threadIdx.x;
    int lane = threadIdx.x & 31, wid = threadIdx.x >> 5;
    int x = (i < NV) ? deg[i] : 0;
#pragma unroll
    for (int d = 1; d < 32; d <<= 1) {
        int t = __shfl_up_sync(0xffffffffu, x, d);
        if (lane >= d) x += t;
    }
    if (lane == 31) ws[wid] = x;
    __syncthreads();
    if (wid == 0) {
        int w = ws[lane];
#pragma unroll
        for (int d = 1; d < 32; d <<= 1) {
            int t = __shfl_up_sync(0xffffffffu, w, d);
            if (lane >= d) w += t;
        }
        ws[lane] = w;
    }
    __syncthreads();
    int off = (wid > 0) ? ws[wid - 1] : 0;
    int v = x + off;
    if (i < NV) incl[i] = v;
    if (threadIdx.x == 1023) bsum[blockIdx.x] = v;
}

__global__ void scan2(int* bsum)
{
    if (threadIdx.x == 0 && blockIdx.x == 0) {
        int acc = 0;
        for (int b = 0; b < NB_SCAN; b++) { int t = bsum[b]; bsum[b] = acc; acc += t; }
    }
}

__global__ __launch_bounds__(256)
void scan3(const int* __restrict__ incl, const int* __restrict__ deg,
           const int* __restrict__ bsum, int* __restrict__ indptr,
           int* __restrict__ cursor)
{
    int i = blockIdx.x * blockDim.x + threadIdx.x;
    if (i >= NV) return;
    int total = incl[i] + bsum[i >> 10];
    int ex = total - deg[i];
    indptr[i] = ex;
    cursor[i] = ex;
    if (i == NV - 1) indptr[NV] = total;
}

__global__ __launch_bounds__(256)
void fill_adj(const int2* __restrict__ edges, int* __restrict__ cursor,
              int* __restrict__ adj)
{
    int t = blockIdx.x * blockDim.x + threadIdx.x;
    if (t >= NE) return;
    int2 e = edges[t];
    int p = atomicAdd(&cursor[e.x], 1); adj[p] = e.y;
    int q = atomicAdd(&cursor[e.y], 1); adj[q] = e.x;
}

// ---------------------------------------------------------------------------
// Weight pre-split: all 13 layers' (W0|W1) fp32 -> bf16 hi/lo planes
// ---------------------------------------------------------------------------
__global__ __launch_bounds__(256)
void wsplit(const float* __restrict__ W0_1, const float* __restrict__ W1_1,
            const float* __restrict__ W0_h, const float* __restrict__ W1_h,
            __nv_bfloat16* __restrict__ WH, __nv_bfloat16* __restrict__ WL)
{
    int idx = blockIdx.x * blockDim.x + threadIdx.x;   // float4 units
    if (idx >= 13 * 256 * 32) return;
    int layer = idx / (256 * 32);
    int rem   = idx % (256 * 32);
    int row   = rem >> 5;
    int c4    = (rem & 31) * 4;
    const float* src;
    if (layer == 0)
        src = (row < 128) ? (W0_1 + (size_t)row * 128) : (W1_1 + (size_t)(row - 128) * 128);
    else
        src = (row < 128) ? (W0_h + (size_t)(layer - 1) * 16384 + (size_t)row * 128)
                          : (W1_h + (size_t)(layer - 1) * 16384 + (size_t)(row - 128) * 128);
    float4 v = *(const float4*)(src + c4);
    __nv_bfloat16 h0 = __float2bfloat16_rn(v.x), h1 = __float2bfloat16_rn(v.y);
    __nv_bfloat16 h2 = __float2bfloat16_rn(v.z), h3 = __float2bfloat16_rn(v.w);
    float l0 = v.x - __bfloat162float(h0), l1 = v.y - __bfloat162float(h1);
    float l2 = v.z - __bfloat162float(h2), l3 = v.w - __bfloat162float(h3);
    size_t o = ((size_t)(layer * 256 + row) << 7) + c4;
    *(uint2*)(WH + o) = make_uint2(pk(h0, h1), pk(h2, h3));
    *(uint2*)(WL + o) = make_uint2(pk(__float2bfloat16_rn(l0), __float2bfloat16_rn(l1)),
                                   pk(__float2bfloat16_rn(l2), __float2bfloat16_rn(l3)));
}

// features fp32 -> hi/lo planes (no relu)
__global__ __launch_bounds__(256)
void featsplit(const float4* __restrict__ X, __nv_bfloat16* __restrict__ AH,
               __nv_bfloat16* __restrict__ AL)
{
    int idx = blockIdx.x * blockDim.x + threadIdx.x;   // float4 units
    if (idx >= NV * 32) return;
    float4 v = X[idx];
    __nv_bfloat16 h0 = __float2bfloat16_rn(v.x), h1 = __float2bfloat16_rn(v.y);
    __nv_bfloat16 h2 = __float2bfloat16_rn(v.z), h3 = __float2bfloat16_rn(v.w);
    float l0 = v.x - __bfloat162float(h0), l1 = v.y - __bfloat162float(h1);
    float l2 = v.z - __bfloat162float(h2), l3 = v.w - __bfloat162float(h3);
    *(uint2*)(AH + (size_t)idx * 4) = make_uint2(pk(h0, h1), pk(h2, h3));
    *(uint2*)(AL + (size_t)idx * 4) =
        make_uint2(pk(__float2bfloat16_rn(l0), __float2bfloat16_rn(l1)),
                   pk(__float2bfloat16_rn(l2), __float2bfloat16_rn(l3)));
}

// ---------------------------------------------------------------------------
// CSR gather-aggregate: x = relu(Y[v] + sum_{j in adj(v)} N[j]); emit hi/lo
// planes for the next layer. Warp per vertex, lane = one float4.
// ---------------------------------------------------------------------------
__global__ __launch_bounds__(256)
void agg_csr(const float4* __restrict__ Y, const float4* __restrict__ Nb,
             const int* __restrict__ indptr, const int* __restrict__ adj,
             __nv_bfloat16* __restrict__ AH, __nv_bfloat16* __restrict__ AL)
{
    int w = (blockIdx.x * blockDim.x + threadIdx.x) >> 5;
    int lane = threadIdx.x & 31;
    if (w >= NV) return;
    float4 acc = Y[(size_t)w * 32 + lane];
    int s = indptr[w], e = indptr[w + 1];
    for (int k = s; k < e; k++) {
        int j = adj[k];
        float4 n = Nb[(size_t)j * 32 + lane];
        acc.x += n.x; acc.y += n.y; acc.z += n.z; acc.w += n.w;
    }
    acc.x = fmaxf(acc.x, 0.f); acc.y = fmaxf(acc.y, 0.f);
    acc.z = fmaxf(acc.z, 0.f); acc.w = fmaxf(acc.w, 0.f);
    __nv_bfloat16 h0 = __float2bfloat16_rn(acc.x), h1 = __float2bfloat16_rn(acc.y);
    __nv_bfloat16 h2 = __float2bfloat16_rn(acc.z), h3 = __float2bfloat16_rn(acc.w);
    float l0 = acc.x - __bfloat162float(h0), l1 = acc.y - __bfloat162float(h1);
    float l2 = acc.z - __bfloat162float(h2), l3 = acc.w - __bfloat162float(h3);
    size_t o = ((size_t)w << 7) + lane * 4;
    *(uint2*)(AH + o) = make_uint2(pk(h0, h1), pk(h2, h3));
    *(uint2*)(AL + o) = make_uint2(pk(__float2bfloat16_rn(l0), __float2bfloat16_rn(l1)),
                                   pk(__float2bfloat16_rn(l2), __float2bfloat16_rn(l3)));
}

// ---------------------------------------------------------------------------
// Final layer: z = (Rh+Rl) + (Ah+Al); y = z@W0l^T + b0l; n = z@W1l^T + b1l
// ---------------------------------------------------------------------------
__global__ __launch_bounds__(256)
void final_gemm(const __nv_bfloat16* __restrict__ Rh, const __nv_bfloat16* __restrict__ Rl,
                const __nv_bfloat16* __restrict__ Ahp, const __nv_bfloat16* __restrict__ Alp,
                const float* __restrict__ W0, const float* __restrict__ b0,
                const float* __restrict__ W1, const float* __restrict__ b1,
                float* __restrict__ Yout /*NV*3*/, float* __restrict__ Nl /*NV*3*/)
{
    __shared__ float w[6][128];
    int tid = threadIdx.x;
    for (int i = tid; i < 384; i += blockDim.x) {
        w[i / 128][i % 128]     = W0[i];
        w[3 + i / 128][i % 128] = W1[i];
    }
    __syncthreads();

    int row  = blockIdx.x * (blockDim.x >> 5) + (tid >> 5);
    int lane = tid & 31;
    if (row >= NV) return;

    size_t o = ((size_t)row << 7) + lane * 4;
    uint2 rh = *(const uint2*)(Rh + o), rl = *(const uint2*)(Rl + o);
    uint2 ah = *(const uint2*)(Ahp + o), al = *(const uint2*)(Alp + o);
    float2 a0 = up2(rh.x), a1 = up2(rh.y), b0f = up2(rl.x), b1f = up2(rl.y);
    float2 c0 = up2(ah.x), c1 = up2(ah.y), d0 = up2(al.x), d1 = up2(al.y);
    float4 z;
    z.x = (a0.x + b0f.x) + (c0.x + d0.x);
    z.y = (a0.y + b0f.y) + (c0.y + d0.y);
    z.z = (a1.x + b1f.x) + (c1.x + d1.x);
    z.w = (a1.y + b1f.y) + (c1.y + d1.y);

    float s[6];
#pragma unroll
    for (int oo = 0; oo < 6; oo++) {
        float4 wv = ((const float4*)w[oo])[lane];
        s[oo] = z.x * wv.x + z.y * wv.y + z.z * wv.z + z.w * wv.w;
    }
#pragma unroll
    for (int off = 16; off > 0; off >>= 1)
#pragma unroll
        for (int oo = 0; oo < 6; oo++)
            s[oo] += __shfl_down_sync(0xffffffffu, s[oo], off);

    if (lane == 0) {
#pragma unroll
        for (int oo = 0; oo < 3; oo++) {
            Yout[(size_t)row * 3 + oo] = s[oo] + b0[oo];
            Nl[(size_t)row * 3 + oo]   = s[3 + oo] + b1[oo];
        }
    }
}

// Final scatter over D_OUT=3: one thread per edge, scalar atomics.
__global__ __launch_bounds__(256)
void scatter3(const float* __restrict__ Nl, const int2* __restrict__ edges,
              float* __restrict__ Out)
{
    int t = blockIdx.x * blockDim.x + threadIdx.x;
    if (t >= NE) return;
    int2 e = edges[t];
#pragma unroll
    for (int o = 0; o < 3; o++) {
        atomicAdd(Out + (size_t)e.x * 3 + o, Nl[(size_t)e.y * 3 + o]);
        atomicAdd(Out + (size_t)e.y * 3 + o, Nl[(size_t)e.x * 3 + o]);
    }
}

// auxiliary = hi+lo reconstruction of relu(last hidden output)
__global__ __launch_bounds__(256)
void aux_sum(const __nv_bfloat16* __restrict__ AH, const __nv_bfloat16* __restrict__ AL,
             float4* __restrict__ out)
{
    int idx = blockIdx.x * blockDim.x + threadIdx.x;   // float4 units
    if (idx >= NV * 32) return;
    uint2 h = *(const uint2*)(AH + (size_t)idx * 4);
    uint2 l = *(const uint2*)(AL + (size_t)idx * 4);
    float2 h0 = up2(h.x), h1 = up2(h.y), l0 = up2(l.x), l1 = up2(l.y);
    out[idx] = make_float4(h0.x + l0.x, h0.y + l0.y, h1.x + l1.x, h1.y + l1.y);
}

// ---------------------------------------------------------------------------
extern "C" void kernel_launch(void* const* d_in, const int* in_sizes, int n_in,
                              void* d_out, int out_size)
{
    const float* features = (const float*)d_in[0];
    const int2*  edges    = (const int2*)d_in[1];
    const float* W0_1 = (const float*)d_in[2];
    const float* b0_1 = (const float*)d_in[3];
    const float* W1_1 = (const float*)d_in[4];
    const float* b1_1 = (const float*)d_in[5];
    const float* W0_h = (const float*)d_in[6];
    const float* b0_h = (const float*)d_in[7];
    const float* W1_h = (const float*)d_in[8];
    const float* b1_h = (const float*)d_in[9];
    const float* W0_l = (const float*)d_in[10];
    const float* b0_l = (const float*)d_in[11];
    const float* W1_l = (const float*)d_in[12];
    const float* b1_l = (const float*)d_in[13];
    float* out = (float*)d_out;   // [vertices NV*3 | auxiliary NV*128]

    float *Y, *N, *NL;
    __nv_bfloat16 *Ah, *Al, *Rh, *Rl, *WH, *WL;
    int *deg, *incl, *bsum, *indptr, *cursor, *adj;
    cudaGetSymbolAddress((void**)&Y,  g_Y);
    cudaGetSymbolAddress((void**)&N,  g_N);
    cudaGetSymbolAddress((void**)&NL, g_NL);
    cudaGetSymbolAddress((void**)&Ah, g_Ah);
    cudaGetSymbolAddress((void**)&Al, g_Al);
    cudaGetSymbolAddress((void**)&Rh, g_Rh);
    cudaGetSymbolAddress((void**)&Rl, g_Rl);
    cudaGetSymbolAddress((void**)&WH, g_WH);
    cudaGetSymbolAddress((void**)&WL, g_WL);
    cudaGetSymbolAddress((void**)&deg,    g_deg);
    cudaGetSymbolAddress((void**)&incl,   g_incl);
    cudaGetSymbolAddress((void**)&bsum,   g_bsum);
    cudaGetSymbolAddress((void**)&indptr, g_indptr);
    cudaGetSymbolAddress((void**)&cursor, g_cursor);
    cudaGetSymbolAddress((void**)&adj,    g_adj);

    cudaFuncSetAttribute(gemm_dual_tc,
                         cudaFuncAttributeMaxDynamicSharedMemorySize, SMEM_TOTAL);

    int dev = 0, sms = 148;
    cudaGetDevice(&dev);
    cudaDeviceGetAttribute(&sms, cudaDevAttrMultiProcessorCount, dev);
    const int gemmBlocks = (sms < NT64) ? sms : NT64;   // persistent: 1 CTA/SM
    const int aggBlocks  = (NV * 32 + 255) / 256;       // warp per vertex
    const int edgeBlocks = (NE + 255) / 256;

    // ---- CSR build (edges static; rebuilt each call for determinism) ----
    cudaMemsetAsync(deg, 0, NV * sizeof(int));
    deg_count<<<edgeBlocks, 256>>>(edges, deg);
    scan1<<<NB_SCAN, 1024>>>(deg, incl, bsum);
    scan2<<<1, 32>>>(bsum);
    scan3<<<(NV + 255) / 256, 256>>>(incl, deg, bsum, indptr, cursor);
    fill_adj<<<edgeBlocks, 256>>>(edges, cursor, adj);

    // ---- one-time conversions ----
    wsplit<<<(13 * 256 * 32 + 255) / 256, 256>>>(W0_1, W1_1, W0_h, W1_h, WH, WL);
    featsplit<<<(NV * 32 + 255) / 256, 256>>>((const float4*)features, Ah, Al);

    // ---- layer 1 (in -> hidden) ----
    gemm_dual_tc<<<gemmBlocks, 256, SMEM_TOTAL>>>(Ah, Al, WH, WL, b0_1, b1_1, Y, N);
    agg_csr<<<aggBlocks, 256>>>((const float4*)Y, (const float4*)N, indptr, adj, Rh, Rl);

    // ---- 12 hidden layers ----
    const __nv_bfloat16* ih = Rh;
    const __nv_bfloat16* il = Rl;
    for (int l = 0; l < LHID; l++) {
        gemm_dual_tc<<<gemmBlocks, 256, SMEM_TOTAL>>>(
            ih, il, WH + (size_t)(1 + l) * 256 * 128, WL + (size_t)(1 + l) * 256 * 128,
            b0_h + l * DH, b1_h + l * DH, Y, N);
        agg_csr<<<aggBlocks, 256>>>((const float4*)Y, (const float4*)N, indptr, adj, Ah, Al);
        ih = Ah; il = Al;
    }
    // Ah/Al now hold relu(last hidden output) planes.

    // ---- final layer: z = relu(residual) + relu(x_last) ----
    final_gemm<<<(NV + 7) / 8, 256>>>(Rh, Rl, Ah, Al, W0_l, b0_l, W1_l, b1_l, out, NL);
    scatter3<<<edgeBlocks, 256>>>(NL, edges, out);

    // ---- auxiliary ----
    aux_sum<<<(NV * 32 + 255) / 256, 256>>>(Ah, Al, (float4*)(out + (size_t)NV * 3));
}

// round 7
// speedup vs baseline: 2.7277x; 1.0414x over previous
#include <cuda_runtime.h>
#include <cuda_bf16.h>
#include <cstdint>

#define NV 100000
#define NE 300000
#define DH 128
#define LHID 12
#define NB_SCAN 98   // ceil(NV/1024)
#define NT64 1563    // ceil(NV/64) A-tiles

// ---------------- scratch (static device globals; no allocation allowed) ---
__device__ float g_Y[NV * DH];              // self-transform output (fp32)
__device__ float g_N[NV * DH];              // neighbor-transform output (fp32)
__device__ __nv_bfloat16 g_Ah[NV * DH];     // current layer input, hi plane
__device__ __nv_bfloat16 g_Al[NV * DH];     // current layer input, lo plane
__device__ __nv_bfloat16 g_Rh[NV * DH];     // residual (layer-1 out) hi
__device__ __nv_bfloat16 g_Rl[NV * DH];     // residual lo
__device__ __nv_bfloat16 g_WH[13 * 256 * DH];  // pre-split weights hi (W0|W1 per layer)
__device__ __nv_bfloat16 g_WL[13 * 256 * DH];  // pre-split weights lo
__device__ float g_NL[NV * 3];              // final-layer neighbor transform
// CSR build
__device__ int g_deg[NV];
__device__ int g_incl[NV];
__device__ int g_bsum[NB_SCAN];
__device__ int g_indptr[NV + 1];
__device__ int g_cursor[NV];
__device__ int g_adj[2 * NE];

// ======================= helpers ===========================================
__device__ __forceinline__ uint32_t smem_u32(const void* p) {
    uint32_t a;
    asm("{ .reg .u64 t; cvta.to.shared.u64 t, %1; cvt.u32.u64 %0, t; }"
        : "=r"(a) : "l"(p));
    return a;
}
__device__ __forceinline__ void ldmatrix_x4(uint32_t* r, uint32_t addr) {
    asm volatile("ldmatrix.sync.aligned.m8n8.x4.shared.b16 {%0,%1,%2,%3}, [%4];"
                 : "=r"(r[0]), "=r"(r[1]), "=r"(r[2]), "=r"(r[3]) : "r"(addr));
}
__device__ __forceinline__ void mma16816(float* c, const uint32_t* a, const uint32_t* b) {
    asm volatile(
        "mma.sync.aligned.m16n8k16.row.col.f32.bf16.bf16.f32 "
        "{%0,%1,%2,%3}, {%4,%5,%6,%7}, {%8,%9}, {%0,%1,%2,%3};"
        : "+f"(c[0]), "+f"(c[1]), "+f"(c[2]), "+f"(c[3])
        : "r"(a[0]), "r"(a[1]), "r"(a[2]), "r"(a[3]), "r"(b[0]), "r"(b[1]));
}
__device__ __forceinline__ uint32_t pk(__nv_bfloat16 a, __nv_bfloat16 b) {
    uint16_t ua = *(uint16_t*)&a, ub = *(uint16_t*)&b;
    return (uint32_t)ua | ((uint32_t)ub << 16);
}
__device__ __forceinline__ float2 up2(uint32_t p) {
    __nv_bfloat162 b = *reinterpret_cast<__nv_bfloat162*>(&p);
    return make_float2(__bfloat162float(b.x), __bfloat162float(b.y));
}
__device__ __forceinline__ void cp16(uint32_t dst, const void* src) {
    asm volatile("cp.async.cg.shared.global [%0], [%1], 16;"
                 :: "r"(dst), "l"(src));
}
__device__ __forceinline__ float4 ldcs4(const float4* p) {
    float4 v;
    asm volatile("ld.global.cs.v4.f32 {%0,%1,%2,%3}, [%4];"
                 : "=f"(v.x), "=f"(v.y), "=f"(v.z), "=f"(v.w) : "l"(p));
    return v;
}

// SMEM layout (bytes). Row stride 272 = 17*16B -> conflict-free ldmatrix.
#define TSTR 272
#define OFF_BIAS 0
#define OFF_A0   1024
#define A_PLANE  17408                      // 64*272 per plane
#define A_BUF    34816                      // hi+lo
#define OFF_A1   (OFF_A0 + A_BUF)           // 35840
#define OFF_BH   (OFF_A1 + A_BUF)           // 70656
#define OFF_BL   (OFF_BH + 256 * TSTR)      // 140288
#define SMEM_TOTAL (OFF_BL + 256 * TSTR)    // 209920

// ---------------------------------------------------------------------------
// Persistent, pipelined tensor-core dual GEMM (split-bf16, 3xMMA, fp32-class):
//   Yout[m,0:128] = X @ W0^T + b0 ;  Nbuf[m,0:128] = X @ W1^T + b1
// Grid = #SM CTAs. Each CTA: load B (weights) ONCE, then loop over 64-row
// A-tiles with stride gridDim, double-buffered cp.async A prefetch.
// 8 warps = 2(M) x 4(N), warp 32x64.
// ---------------------------------------------------------------------------
__global__ __launch_bounds__(256, 1)
void gemm_dual_tc(const __nv_bfloat16* __restrict__ XH,
                  const __nv_bfloat16* __restrict__ XL,
                  const __nv_bfloat16* __restrict__ WH,   // layer base [256][128]
                  const __nv_bfloat16* __restrict__ WL,
                  const float* __restrict__ b0, const float* __restrict__ b1,
                  float* __restrict__ Yout, float* __restrict__ Nbuf)
{
    extern __shared__ char smem[];
    const uint32_t sb = smem_u32(smem);
    const int tid  = threadIdx.x;
    const int wid  = tid >> 5;
    const int lane = tid & 31;

    // bias into smem
    ((float*)(smem + OFF_BIAS))[tid] = (tid < 128) ? b0[tid] : b1[tid - 128];

    // ---- B tiles via cp.async (once per layer per CTA) ----
#pragma unroll
    for (int i = 0; i < 16; i++) {
        int c = tid + i * 256;
        int n = c >> 4, kc = c & 15;
        uint32_t so = (uint32_t)(n * TSTR + kc * 16);
        const size_t go = ((size_t)n << 7) + kc * 8;
        cp16(sb + OFF_BH + so, WH + go);
        cp16(sb + OFF_BL + so, WL + go);
    }

    // A-tile issue helper (64 rows x 256B per plane)
    auto issueA = [&](int t, int buf) {
        const uint32_t abase = sb + (buf ? OFF_A1 : OFF_A0);
        char* abasep = smem + (buf ? OFF_A1 : OFF_A0);
        const int m0 = t * 64;
#pragma unroll
        for (int i = 0; i < 4; i++) {
            int c = tid + i * 256;
            int r = c >> 4, kc = c & 15;
            int grow = m0 + r;
            uint32_t so = (uint32_t)(r * TSTR + kc * 16);
            if (grow < NV) {
                const size_t go = ((size_t)grow << 7) + kc * 8;
                cp16(abase + so, XH + go);
                cp16(abase + A_PLANE + so, XL + go);
            } else {
                *(uint4*)(abasep + so) = make_uint4(0, 0, 0, 0);
                *(uint4*)(abasep + A_PLANE + so) = make_uint4(0, 0, 0, 0);
            }
        }
    };

    int t = blockIdx.x;
    if (t >= NT64) return;
    issueA(t, 0);
    asm volatile("cp.async.commit_group;");

    // warp tiling constants
    const int wm = wid & 1;
    const int wn = wid >> 1;
    const uint32_t a_roff = (uint32_t)((wm * 32 + (lane & 15)) * TSTR + ((lane >> 4) * 8) * 2);
    const uint32_t b_n    = (uint32_t)(wn * 64 + (lane & 7) + ((lane >> 4) * 8));
    const uint32_t b_kh   = (uint32_t)(((lane >> 3) & 1) * 8);
    const uint32_t b_base = sb + OFF_BH + b_n * TSTR + b_kh * 2;
    const int g = lane >> 2;
    const int tq = lane & 3;
    const bool isY = (wn < 2);
    float* dbase = isY ? Yout : Nbuf;
    const float* bs = (const float*)(smem + OFF_BIAS);

    int p = 0;
    while (t < NT64) {
        const int tn = t + gridDim.x;
        if (tn < NT64) {
            issueA(tn, p ^ 1);
            asm volatile("cp.async.commit_group;");
            asm volatile("cp.async.wait_group 1;");
        } else {
            asm volatile("cp.async.wait_group 0;");
        }
        __syncthreads();

        const uint32_t a_base = sb + (p ? OFF_A1 : OFF_A0) + a_roff;

        float acc[2][8][4];
#pragma unroll
        for (int mt = 0; mt < 2; mt++)
#pragma unroll
            for (int nt = 0; nt < 8; nt++)
#pragma unroll
                for (int q = 0; q < 4; q++) acc[mt][nt][q] = 0.f;

#pragma unroll
        for (int s = 0; s < 8; s++) {
            uint32_t Ahf[2][4], Alf[2][4], Bhf[4][4], Blf[4][4];
#pragma unroll
            for (int mt = 0; mt < 2; mt++) {
                uint32_t ad = a_base + (uint32_t)(mt * 16 * TSTR + s * 32);
                ldmatrix_x4(Ahf[mt], ad);
                ldmatrix_x4(Alf[mt], ad + A_PLANE);
            }
#pragma unroll
            for (int q = 0; q < 4; q++) {
                uint32_t bd = b_base + (uint32_t)(q * 16 * TSTR + s * 32);
                ldmatrix_x4(Bhf[q], bd);
                ldmatrix_x4(Blf[q], bd + (OFF_BL - OFF_BH));
            }
#pragma unroll
            for (int mt = 0; mt < 2; mt++)
#pragma unroll
                for (int nt = 0; nt < 8; nt++) {
                    const uint32_t* bh = &Bhf[nt >> 1][(nt & 1) * 2];
                    const uint32_t* bl = &Blf[nt >> 1][(nt & 1) * 2];
                    mma16816(acc[mt][nt], Ahf[mt], bh);   // hi*hi
                    mma16816(acc[mt][nt], Alf[mt], bh);   // lo*hi
                    mma16816(acc[mt][nt], Ahf[mt], bl);   // hi*lo
                }
        }

        // ---- epilogue: bias + guarded float2 stores ----
        const int m0 = t * 64;
#pragma unroll
        for (int mt = 0; mt < 2; mt++) {
            int row0 = m0 + wm * 32 + mt * 16 + g;
#pragma unroll
            for (int nt = 0; nt < 8; nt++) {
                int col = wn * 64 + nt * 8 + tq * 2;
                float b0v = bs[col], b1v = bs[col + 1];
                int cc = isY ? col : (col - 128);
                if (row0 < NV) {
                    float2 o = make_float2(acc[mt][nt][0] + b0v, acc[mt][nt][1] + b1v);
                    *(float2*)(dbase + (size_t)row0 * 128 + cc) = o;
                }
                if (row0 + 8 < NV) {
                    float2 o = make_float2(acc[mt][nt][2] + b0v, acc[mt][nt][3] + b1v);
                    *(float2*)(dbase + (size_t)(row0 + 8) * 128 + cc) = o;
                }
            }
        }
        __syncthreads();   // protect buf p before next prefetch overwrites it
        t = tn;
        p ^= 1;
    }
}

// ---------------------------------------------------------------------------
// CSR build kernels (edges are static; built once per launch)
// ---------------------------------------------------------------------------
__global__ __launch_bounds__(256)
void deg_count(const int2* __restrict__ edges, int* __restrict__ deg)
{
    int t = blockIdx.x * blockDim.x + threadIdx.x;
    if (t >= NE) return;
    int2 e = edges[t];
    atomicAdd(&deg[e.x], 1);
    atomicAdd(&deg[e.y], 1);
}

__global__ __launch_bounds__(1024)
void scan1(const int* __restrict__ deg, int* __restrict__ incl, int* __restrict__ bsum)
{
    __shared__ int ws[32];
    int i = blockIdx.x * 1024 + threadIdx.x;
    int lane = threadIdx.x & 31, wid = threadIdx.x >> 5;
    int x = (i < NV) ? deg[i] : 0;
#pragma unroll
    for (int d = 1; d < 32; d <<= 1) {
        int t = __shfl_up_sync(0xffffffffu, x, d);
        if (lane >= d) x += t;
    }
    if (lane == 31) ws[wid] = x;
    __syncthreads();
    if (wid == 0) {
        int w = ws[lane];
#pragma unroll
        for (int d = 1; d < 32; d <<= 1) {
            int t = __shfl_up_sync(0xffffffffu, w, d);
            if (lane >= d) w += t;
        }
        ws[lane] = w;
    }
    __syncthreads();
    int off = (wid > 0) ? ws[wid - 1] : 0;
    int v = x + off;
    if (i < NV) incl[i] = v;
    if (threadIdx.x == 1023) bsum[blockIdx.x] = v;
}

__global__ void scan2(int* bsum)
{
    if (threadIdx.x == 0 && blockIdx.x == 0) {
        int acc = 0;
        for (int b = 0; b < NB_SCAN; b++) { int t = bsum[b]; bsum[b] = acc; acc += t; }
    }
}

__global__ __launch_bounds__(256)
void scan3(const int* __restrict__ incl, const int* __restrict__ deg,
           const int* __restrict__ bsum, int* __restrict__ indptr,
           int* __restrict__ cursor)
{
    int i = blockIdx.x * blockDim.x + threadIdx.x;
    if (i >= NV) return;
    int total = incl[i] + bsum[i >> 10];
    int ex = total - deg[i];
    indptr[i] = ex;
    cursor[i] = ex;
    if (i == NV - 1) indptr[NV] = total;
}

__global__ __launch_bounds__(256)
void fill_adj(const int2* __restrict__ edges, int* __restrict__ cursor,
              int* __restrict__ adj)
{
    int t = blockIdx.x * blockDim.x + threadIdx.x;
    if (t >= NE) return;
    int2 e = edges[t];
    int p = atomicAdd(&cursor[e.x], 1); adj[p] = e.y;
    int q = atomicAdd(&cursor[e.y], 1); adj[q] = e.x;
}

// ---------------------------------------------------------------------------
// Weight pre-split: all 13 layers' (W0|W1) fp32 -> bf16 hi/lo planes
// ---------------------------------------------------------------------------
__global__ __launch_bounds__(256)
void wsplit(const float* __restrict__ W0_1, const float* __restrict__ W1_1,
            const float* __restrict__ W0_h, const float* __restrict__ W1_h,
            __nv_bfloat16* __restrict__ WH, __nv_bfloat16* __restrict__ WL)
{
    int idx = blockIdx.x * blockDim.x + threadIdx.x;   // float4 units
    if (idx >= 13 * 256 * 32) return;
    int layer = idx / (256 * 32);
    int rem   = idx % (256 * 32);
    int row   = rem >> 5;
    int c4    = (rem & 31) * 4;
    const float* src;
    if (layer == 0)
        src = (row < 128) ? (W0_1 + (size_t)row * 128) : (W1_1 + (size_t)(row - 128) * 128);
    else
        src = (row < 128) ? (W0_h + (size_t)(layer - 1) * 16384 + (size_t)row * 128)
                          : (W1_h + (size_t)(layer - 1) * 16384 + (size_t)(row - 128) * 128);
    float4 v = *(const float4*)(src + c4);
    __nv_bfloat16 h0 = __float2bfloat16_rn(v.x), h1 = __float2bfloat16_rn(v.y);
    __nv_bfloat16 h2 = __float2bfloat16_rn(v.z), h3 = __float2bfloat16_rn(v.w);
    float l0 = v.x - __bfloat162float(h0), l1 = v.y - __bfloat162float(h1);
    float l2 = v.z - __bfloat162float(h2), l3 = v.w - __bfloat162float(h3);
    size_t o = ((size_t)(layer * 256 + row) << 7) + c4;
    *(uint2*)(WH + o) = make_uint2(pk(h0, h1), pk(h2, h3));
    *(uint2*)(WL + o) = make_uint2(pk(__float2bfloat16_rn(l0), __float2bfloat16_rn(l1)),
                                   pk(__float2bfloat16_rn(l2), __float2bfloat16_rn(l3)));
}

// features fp32 -> hi/lo planes (no relu)
__global__ __launch_bounds__(256)
void featsplit(const float4* __restrict__ X, __nv_bfloat16* __restrict__ AH,
               __nv_bfloat16* __restrict__ AL)
{
    int idx = blockIdx.x * blockDim.x + threadIdx.x;   // float4 units
    if (idx >= NV * 32) return;
    float4 v = X[idx];
    __nv_bfloat16 h0 = __float2bfloat16_rn(v.x), h1 = __float2bfloat16_rn(v.y);
    __nv_bfloat16 h2 = __float2bfloat16_rn(v.z), h3 = __float2bfloat16_rn(v.w);
    float l0 = v.x - __bfloat162float(h0), l1 = v.y - __bfloat162float(h1);
    float l2 = v.z - __bfloat162float(h2), l3 = v.w - __bfloat162float(h3);
    *(uint2*)(AH + (size_t)idx * 4) = make_uint2(pk(h0, h1), pk(h2, h3));
    *(uint2*)(AL + (size_t)idx * 4) =
        make_uint2(pk(__float2bfloat16_rn(l0), __float2bfloat16_rn(l1)),
                   pk(__float2bfloat16_rn(l2), __float2bfloat16_rn(l3)));
}

// ---------------------------------------------------------------------------
// CSR gather-aggregate: x = relu(Y[v] + sum_{j in adj(v)} N[j]); emit hi/lo
// planes for the next layer. Warp per vertex, lane = one float4.
// 4-way index batch -> MLP=4 on the 512B row gathers.
// ---------------------------------------------------------------------------
__global__ __launch_bounds__(256)
void agg_csr(const float4* __restrict__ Y, const float4* __restrict__ Nb,
             const int* __restrict__ indptr, const int* __restrict__ adj,
             __nv_bfloat16* __restrict__ AH, __nv_bfloat16* __restrict__ AL)
{
    int w = (blockIdx.x * blockDim.x + threadIdx.x) >> 5;
    int lane = threadIdx.x & 31;
    if (w >= NV) return;
    float4 acc = ldcs4(Y + (size_t)w * 32 + lane);   // streaming read, evict-first
    const int s = indptr[w], e = indptr[w + 1];
    int k = s;
    for (; k + 4 <= e; k += 4) {
        int j0 = __ldg(adj + k);
        int j1 = __ldg(adj + k + 1);
        int j2 = __ldg(adj + k + 2);
        int j3 = __ldg(adj + k + 3);
        float4 n0 = Nb[(size_t)j0 * 32 + lane];
        float4 n1 = Nb[(size_t)j1 * 32 + lane];
        float4 n2 = Nb[(size_t)j2 * 32 + lane];
        float4 n3 = Nb[(size_t)j3 * 32 + lane];
        acc.x += (n0.x + n1.x) + (n2.x + n3.x);
        acc.y += (n0.y + n1.y) + (n2.y + n3.y);
        acc.z += (n0.z + n1.z) + (n2.z + n3.z);
        acc.w += (n0.w + n1.w) + (n2.w + n3.w);
    }
    if (k + 2 <= e) {
        int j0 = __ldg(adj + k);
        int j1 = __ldg(adj + k + 1);
        float4 n0 = Nb[(size_t)j0 * 32 + lane];
        float4 n1 = Nb[(size_t)j1 * 32 + lane];
        acc.x += n0.x + n1.x; acc.y += n0.y + n1.y;
        acc.z += n0.z + n1.z; acc.w += n0.w + n1.w;
        k += 2;
    }
    if (k < e) {
        int j0 = __ldg(adj + k);
        float4 n0 = Nb[(size_t)j0 * 32 + lane];
        acc.x += n0.x; acc.y += n0.y; acc.z += n0.z; acc.w += n0.w;
    }
    acc.x = fmaxf(acc.x, 0.f); acc.y = fmaxf(acc.y, 0.f);
    acc.z = fmaxf(acc.z, 0.f); acc.w = fmaxf(acc.w, 0.f);
    __nv_bfloat16 h0 = __float2bfloat16_rn(acc.x), h1 = __float2bfloat16_rn(acc.y);
    __nv_bfloat16 h2 = __float2bfloat16_rn(acc.z), h3 = __float2bfloat16_rn(acc.w);
    float l0 = acc.x - __bfloat162float(h0), l1 = acc.y - __bfloat162float(h1);
    float l2 = acc.z - __bfloat162float(h2), l3 = acc.w - __bfloat162float(h3);
    size_t o = ((size_t)w << 7) + lane * 4;
    *(uint2*)(AH + o) = make_uint2(pk(h0, h1), pk(h2, h3));
    *(uint2*)(AL + o) = make_uint2(pk(__float2bfloat16_rn(l0), __float2bfloat16_rn(l1)),
                                   pk(__float2bfloat16_rn(l2), __float2bfloat16_rn(l3)));
}

// ---------------------------------------------------------------------------
// Final layer (+ fused aux emit): z = (Rh+Rl) + (Ah+Al);
//   y = z@W0l^T + b0l; n = z@W1l^T + b1l; aux = Ah+Al
// ---------------------------------------------------------------------------
__global__ __launch_bounds__(256)
void final_gemm(const __nv_bfloat16* __restrict__ Rh, const __nv_bfloat16* __restrict__ Rl,
                const __nv_bfloat16* __restrict__ Ahp, const __nv_bfloat16* __restrict__ Alp,
                const float* __restrict__ W0, const float* __restrict__ b0,
                const float* __restrict__ W1, const float* __restrict__ b1,
                float* __restrict__ Yout /*NV*3*/, float* __restrict__ Nl /*NV*3*/,
                float* __restrict__ Aux /*NV*128*/)
{
    __shared__ float w[6][128];
    int tid = threadIdx.x;
    for (int i = tid; i < 384; i += blockDim.x) {
        w[i / 128][i % 128]     = W0[i];
        w[3 + i / 128][i % 128] = W1[i];
    }
    __syncthreads();

    int row  = blockIdx.x * (blockDim.x >> 5) + (tid >> 5);
    int lane = tid & 31;
    if (row >= NV) return;

    size_t o = ((size_t)row << 7) + lane * 4;
    uint2 rh = *(const uint2*)(Rh + o), rl = *(const uint2*)(Rl + o);
    uint2 ah = *(const uint2*)(Ahp + o), al = *(const uint2*)(Alp + o);
    float2 a0 = up2(rh.x), a1 = up2(rh.y), b0f = up2(rl.x), b1f = up2(rl.y);
    float2 c0 = up2(ah.x), c1 = up2(ah.y), d0 = up2(al.x), d1 = up2(al.y);
    // aux = relu(last hidden) = Ah + Al reconstruction
    float4 ax = make_float4(c0.x + d0.x, c0.y + d0.y, c1.x + d1.x, c1.y + d1.y);
    *(float4*)(Aux + o) = ax;
    float4 z;
    z.x = (a0.x + b0f.x) + ax.x;
    z.y = (a0.y + b0f.y) + ax.y;
    z.z = (a1.x + b1f.x) + ax.z;
    z.w = (a1.y + b1f.y) + ax.w;

    float s[6];
#pragma unroll
    for (int oo = 0; oo < 6; oo++) {
        float4 wv = ((const float4*)w[oo])[lane];
        s[oo] = z.x * wv.x + z.y * wv.y + z.z * wv.z + z.w * wv.w;
    }
#pragma unroll
    for (int off = 16; off > 0; off >>= 1)
#pragma unroll
        for (int oo = 0; oo < 6; oo++)
            s[oo] += __shfl_down_sync(0xffffffffu, s[oo], off);

    if (lane == 0) {
#pragma unroll
        for (int oo = 0; oo < 3; oo++) {
            Yout[(size_t)row * 3 + oo] = s[oo] + b0[oo];
            Nl[(size_t)row * 3 + oo]   = s[3 + oo] + b1[oo];
        }
    }
}

// Final scatter over D_OUT=3: one thread per edge, scalar atomics.
__global__ __launch_bounds__(256)
void scatter3(const float* __restrict__ Nl, const int2* __restrict__ edges,
              float* __restrict__ Out)
{
    int t = blockIdx.x * blockDim.x + threadIdx.x;
    if (t >= NE) return;
    int2 e = edges[t];
#pragma unroll
    for (int o = 0; o < 3; o++) {
        atomicAdd(Out + (size_t)e.x * 3 + o, Nl[(size_t)e.y * 3 + o]);
        atomicAdd(Out + (size_t)e.y * 3 + o, Nl[(size_t)e.x * 3 + o]);
    }
}

// ---------------------------------------------------------------------------
extern "C" void kernel_launch(void* const* d_in, const int* in_sizes, int n_in,
                              void* d_out, int out_size)
{
    const float* features = (const float*)d_in[0];
    const int2*  edges    = (const int2*)d_in[1];
    const float* W0_1 = (const float*)d_in[2];
    const float* b0_1 = (const float*)d_in[3];
    const float* W1_1 = (const float*)d_in[4];
    const float* b1_1 = (const float*)d_in[5];
    const float* W0_h = (const float*)d_in[6];
    const float* b0_h = (const float*)d_in[7];
    const float* W1_h = (const float*)d_in[8];
    const float* b1_h = (const float*)d_in[9];
    const float* W0_l = (const float*)d_in[10];
    const float* b0_l = (const float*)d_in[11];
    const float* W1_l = (const float*)d_in[12];
    const float* b1_l = (const float*)d_in[13];
    float* out = (float*)d_out;   // [vertices NV*3 | auxiliary NV*128]

    float *Y, *N, *NL;
    __nv_bfloat16 *Ah, *Al, *Rh, *Rl, *WH, *WL;
    int *deg, *incl, *bsum, *indptr, *cursor, *adj;
    cudaGetSymbolAddress((void**)&Y,  g_Y);
    cudaGetSymbolAddress((void**)&N,  g_N);
    cudaGetSymbolAddress((void**)&NL, g_NL);
    cudaGetSymbolAddress((void**)&Ah, g_Ah);
    cudaGetSymbolAddress((void**)&Al, g_Al);
    cudaGetSymbolAddress((void**)&Rh, g_Rh);
    cudaGetSymbolAddress((void**)&Rl, g_Rl);
    cudaGetSymbolAddress((void**)&WH, g_WH);
    cudaGetSymbolAddress((void**)&WL, g_WL);
    cudaGetSymbolAddress((void**)&deg,    g_deg);
    cudaGetSymbolAddress((void**)&incl,   g_incl);
    cudaGetSymbolAddress((void**)&bsum,   g_bsum);
    cudaGetSymbolAddress((void**)&indptr, g_indptr);
    cudaGetSymbolAddress((void**)&cursor, g_cursor);
    cudaGetSymbolAddress((void**)&adj,    g_adj);

    cudaFuncSetAttribute(gemm_dual_tc,
                         cudaFuncAttributeMaxDynamicSharedMemorySize, SMEM_TOTAL);

    int dev = 0, sms = 148;
    cudaGetDevice(&dev);
    cudaDeviceGetAttribute(&sms, cudaDevAttrMultiProcessorCount, dev);
    const int gemmBlocks = (sms < NT64) ? sms : NT64;   // persistent: 1 CTA/SM
    const int aggBlocks  = (NV * 32 + 255) / 256;       // warp per vertex
    const int edgeBlocks = (NE + 255) / 256;

    // ---- CSR build (edges static; rebuilt each call for determinism) ----
    cudaMemsetAsync(deg, 0, NV * sizeof(int));
    deg_count<<<edgeBlocks, 256>>>(edges, deg);
    scan1<<<NB_SCAN, 1024>>>(deg, incl, bsum);
    scan2<<<1, 32>>>(bsum);
    scan3<<<(NV + 255) / 256, 256>>>(incl, deg, bsum, indptr, cursor);
    fill_adj<<<edgeBlocks, 256>>>(edges, cursor, adj);

    // ---- one-time conversions ----
    wsplit<<<(13 * 256 * 32 + 255) / 256, 256>>>(W0_1, W1_1, W0_h, W1_h, WH, WL);
    featsplit<<<(NV * 32 + 255) / 256, 256>>>((const float4*)features, Ah, Al);

    // ---- layer 1 (in -> hidden) ----
    gemm_dual_tc<<<gemmBlocks, 256, SMEM_TOTAL>>>(Ah, Al, WH, WL, b0_1, b1_1, Y, N);
    agg_csr<<<aggBlocks, 256>>>((const float4*)Y, (const float4*)N, indptr, adj, Rh, Rl);

    // ---- 12 hidden layers ----
    const __nv_bfloat16* ih = Rh;
    const __nv_bfloat16* il = Rl;
    for (int l = 0; l < LHID; l++) {
        gemm_dual_tc<<<gemmBlocks, 256, SMEM_TOTAL>>>(
            ih, il, WH + (size_t)(1 + l) * 256 * 128, WL + (size_t)(1 + l) * 256 * 128,
            b0_h + l * DH, b1_h + l * DH, Y, N);
        agg_csr<<<aggBlocks, 256>>>((const float4*)Y, (const float4*)N, indptr, adj, Ah, Al);
        ih = Ah; il = Al;
    }
    // Ah/Al now hold relu(last hidden output) planes.

    // ---- final layer (+aux): z = relu(residual) + relu(x_last) ----
    final_gemm<<<(NV + 7) / 8, 256>>>(Rh, Rl, Ah, Al, W0_l, b0_l, W1_l, b1_l,
                                      out, NL, out + (size_t)NV * 3);
    scatter3<<<edgeBlocks, 256>>>(NL, edges, out);
}